// round 7
// baseline (speedup 1.0000x reference)
#include <cuda_runtime.h>
#include <cuda_fp16.h>
#include <cuda_bf16.h>
#include <cstdint>

// ---------------------------------------------------------------------------
// EstimateAdj:
//   h    = relu(features @ W1 + b1)   [N,128]->[N,64]
//   reps = h @ W2 + b2                [N,64]
//   pw[e] = relu(dot(reps[ei0[e]], reps[ei1[e]]))  e < Eo
// Output (float32 concat): reps | pw | total_edge_index | edge_index
//
// R7 vs R6 (80.9us):
//  - edge gather: 8 lanes/edge, ONE LDG.128 per row per thread
//    -> L1tex wavefronts per edge halved (4 -> 2)
//  - index-copy role moved from MLP launch to edge launch (hides under the
//    L2-bound gather's DRAM/issue headroom); MLP launch is now pure MMA MLP
// ---------------------------------------------------------------------------

#define MLP_THREADS 256
#define NODES_PER_BLK 128
#define N_MAX 100000

typedef unsigned int u32;

// fp16 shadow of reps (32 half2 per node = 128B/row) for the edge gather
__device__ __half2 g_reps_h[N_MAX * 32];

// smem layout (bytes):
//  Wt1h [64][136] bf16 : 0      .. 17408
//  Wt1l [64][136] bf16 : 17408  .. 34816
//  Wt2h [64][72]  bf16 : 34816  .. 44032
//  Wt2l [64][72]  bf16 : 44032  .. 53248
//  b1s  [64] f32       : 53248  .. 53504
//  b2s  [64] f32       : 53504  .. 53760
#define SMEM_BYTES 53760
#define W1_STRIDE 136   // 68 words; (68*(8n+g)+t)%32 = (4g+t)%32 -> conflict-free
#define W2_STRIDE 72    // 36 words; same property

__device__ __forceinline__ void mma_bf16(float* c, const u32* a, u32 b0, u32 b1) {
    asm volatile(
        "mma.sync.aligned.m16n8k16.row.col.f32.bf16.bf16.f32 "
        "{%0,%1,%2,%3}, {%4,%5,%6,%7}, {%8,%9}, {%0,%1,%2,%3};"
        : "+f"(c[0]), "+f"(c[1]), "+f"(c[2]), "+f"(c[3])
        : "r"(a[0]), "r"(a[1]), "r"(a[2]), "r"(a[3]), "r"(b0), "r"(b1));
}

// split (x,y) into bf16 hi pair + bf16 residual pair (packed, x in low half)
__device__ __forceinline__ void split2(float x, float y, u32& hi, u32& lo) {
    __nv_bfloat16 bx = __float2bfloat16(x), by = __float2bfloat16(y);
    hi = ((u32)__bfloat16_as_ushort(by) << 16) | (u32)__bfloat16_as_ushort(bx);
    float rx = x - __bfloat162float(bx);
    float ry = y - __bfloat162float(by);
    __nv_bfloat16 cx = __float2bfloat16(rx), cy = __float2bfloat16(ry);
    lo = ((u32)__bfloat16_as_ushort(cy) << 16) | (u32)__bfloat16_as_ushort(cx);
}

// Pure MMA MLP (no copy role anymore).
__global__ void __launch_bounds__(MLP_THREADS)
mlp_mma_kernel(const float* __restrict__ feat,
               const float* __restrict__ W1, const float* __restrict__ b1,
               const float* __restrict__ W2, const float* __restrict__ b2,
               float* __restrict__ reps, int N)
{
    const int tx = threadIdx.x;

    extern __shared__ char smc[];
    __nv_bfloat16* Wt1h = (__nv_bfloat16*)(smc);
    __nv_bfloat16* Wt1l = (__nv_bfloat16*)(smc + 17408);
    __nv_bfloat16* Wt2h = (__nv_bfloat16*)(smc + 34816);
    __nv_bfloat16* Wt2l = (__nv_bfloat16*)(smc + 44032);
    float* b1s = (float*)(smc + 53248);
    float* b2s = (float*)(smc + 53504);

    // Prologue: split W1, W2 to transposed bf16 hi/lo planes.
    for (int idx = tx; idx < 128 * 64; idx += MLP_THREADS) {
        int k = idx >> 6, n = idx & 63;
        float w = W1[idx];
        __nv_bfloat16 hi = __float2bfloat16(w);
        Wt1h[n * W1_STRIDE + k] = hi;
        Wt1l[n * W1_STRIDE + k] = __float2bfloat16(w - __bfloat162float(hi));
    }
    for (int idx = tx; idx < 64 * 64; idx += MLP_THREADS) {
        int k = idx >> 6, n = idx & 63;
        float w = W2[idx];
        __nv_bfloat16 hi = __float2bfloat16(w);
        Wt2h[n * W2_STRIDE + k] = hi;
        Wt2l[n * W2_STRIDE + k] = __float2bfloat16(w - __bfloat162float(hi));
    }
    if (tx < 64) { b1s[tx] = b1[tx]; b2s[tx] = b2[tx]; }
    __syncthreads();

    const int warp = tx >> 5, lane = tx & 31;
    const int g = lane >> 2, t = lane & 3;
    const int r0 = blockIdx.x * NODES_PER_BLK + warp * 16 + g;
    const int r1 = r0 + 8;
    const bool v0 = r0 < N, v1 = r1 < N;
    const float* f0p = feat + (size_t)(v0 ? r0 : 0) * 128 + t * 2;
    const float* f1p = feat + (size_t)(v1 ? r1 : 0) * 128 + t * 2;

    // ---- GEMM1: C[8 n-tiles][4] over K=128 (8 k-steps), 3-pass bf16 ----
    float C[8][4];
    #pragma unroll
    for (int n = 0; n < 8; n++)
        #pragma unroll
        for (int i = 0; i < 4; i++) C[n][i] = 0.f;

    #pragma unroll 2
    for (int kt = 0; kt < 8; kt++) {
        float2 x00 = v0 ? *(const float2*)(f0p + kt * 16)     : make_float2(0.f, 0.f);
        float2 x01 = v0 ? *(const float2*)(f0p + kt * 16 + 8) : make_float2(0.f, 0.f);
        float2 x10 = v1 ? *(const float2*)(f1p + kt * 16)     : make_float2(0.f, 0.f);
        float2 x11 = v1 ? *(const float2*)(f1p + kt * 16 + 8) : make_float2(0.f, 0.f);
        u32 ah[4], al[4];
        split2(x00.x, x00.y, ah[0], al[0]);
        split2(x10.x, x10.y, ah[1], al[1]);
        split2(x01.x, x01.y, ah[2], al[2]);
        split2(x11.x, x11.y, ah[3], al[3]);

        const int kb = kt * 16 + t * 2;
        #pragma unroll
        for (int n = 0; n < 8; n++) {
            const __nv_bfloat16* wh = Wt1h + (n * 8 + g) * W1_STRIDE + kb;
            const __nv_bfloat16* wl = Wt1l + (n * 8 + g) * W1_STRIDE + kb;
            u32 bh0 = *(const u32*)(wh);
            u32 bh1 = *(const u32*)(wh + 8);
            u32 bl0 = *(const u32*)(wl);
            u32 bl1 = *(const u32*)(wl + 8);
            mma_bf16(C[n], ah, bh0, bh1);
            mma_bf16(C[n], ah, bl0, bl1);
            mma_bf16(C[n], al, bh0, bh1);
        }
    }

    // bias + relu -> h (registers), then split into GEMM2 A-frags.
    #pragma unroll
    for (int n = 0; n < 8; n++) {
        float bb0 = b1s[n * 8 + t * 2];
        float bb1 = b1s[n * 8 + t * 2 + 1];
        C[n][0] = fmaxf(C[n][0] + bb0, 0.f);
        C[n][1] = fmaxf(C[n][1] + bb1, 0.f);
        C[n][2] = fmaxf(C[n][2] + bb0, 0.f);
        C[n][3] = fmaxf(C[n][3] + bb1, 0.f);
    }

    u32 a2h[4][4], a2l[4][4];
    #pragma unroll
    for (int kt = 0; kt < 4; kt++) {
        split2(C[2 * kt][0],     C[2 * kt][1],     a2h[kt][0], a2l[kt][0]);
        split2(C[2 * kt][2],     C[2 * kt][3],     a2h[kt][1], a2l[kt][1]);
        split2(C[2 * kt + 1][0], C[2 * kt + 1][1], a2h[kt][2], a2l[kt][2]);
        split2(C[2 * kt + 1][2], C[2 * kt + 1][3], a2h[kt][3], a2l[kt][3]);
    }

    // ---- GEMM2: D[8][4] over K=64 (4 k-steps), 3-pass bf16 ----
    float D[8][4];
    #pragma unroll
    for (int n = 0; n < 8; n++)
        #pragma unroll
        for (int i = 0; i < 4; i++) D[n][i] = 0.f;

    #pragma unroll
    for (int kt = 0; kt < 4; kt++) {
        const int kb = kt * 16 + t * 2;
        #pragma unroll
        for (int n = 0; n < 8; n++) {
            const __nv_bfloat16* wh = Wt2h + (n * 8 + g) * W2_STRIDE + kb;
            const __nv_bfloat16* wl = Wt2l + (n * 8 + g) * W2_STRIDE + kb;
            u32 bh0 = *(const u32*)(wh);
            u32 bh1 = *(const u32*)(wh + 8);
            u32 bl0 = *(const u32*)(wl);
            u32 bl1 = *(const u32*)(wl + 8);
            mma_bf16(D[n], a2h[kt], bh0, bh1);
            mma_bf16(D[n], a2h[kt], bl0, bl1);
            mma_bf16(D[n], a2l[kt], bh0, bh1);
        }
    }

    // Epilogue: bias, store reps (fp32) + fp16 shadow.
    #pragma unroll
    for (int n = 0; n < 8; n++) {
        int c0 = n * 8 + t * 2;
        float bb0 = b2s[c0], bb1 = b2s[c0 + 1];
        if (v0) {
            float2 o = make_float2(D[n][0] + bb0, D[n][1] + bb1);
            *(float2*)(reps + (size_t)r0 * 64 + c0) = o;
            g_reps_h[(size_t)r0 * 32 + (c0 >> 1)] = __floats2half2_rn(o.x, o.y);
        }
        if (v1) {
            float2 o = make_float2(D[n][2] + bb0, D[n][3] + bb1);
            *(float2*)(reps + (size_t)r1 * 64 + c0) = o;
            g_reps_h[(size_t)r1 * 32 + (c0 >> 1)] = __floats2half2_rn(o.x, o.y);
        }
    }
}

__device__ __forceinline__ float dot8h(uint4 a, uint4 b) {
    const __half2* pa = (const __half2*)&a;
    const __half2* pb = (const __half2*)&b;
    float acc = 0.f;
    #pragma unroll
    for (int j = 0; j < 4; j++) {
        float2 x = __half22float2(pa[j]);
        float2 y = __half22float2(pb[j]);
        acc = fmaf(x.x, y.x, acc);
        acc = fmaf(x.y, y.y, acc);
    }
    return acc;
}

// Edge dot products (8 lanes/edge, ONE uint4 per row per thread) + copy role.
__global__ void __launch_bounds__(256)
edge_dot_plus_copy_kernel(const int* __restrict__ ei, long long Eo,
                          float* __restrict__ pw, int N, int edge_blocks,
                          const int* __restrict__ pei, long long Ec,
                          float* __restrict__ out_tei, float* __restrict__ out_ei)
{
    if (blockIdx.x >= edge_blocks) {
        // ---------------- index copy role (vectorized x4) ----------------
        const int tx = threadIdx.x;
        long long i = ((long long)(blockIdx.x - edge_blocks) * 256 + tx) * 4;
        long long Et = Eo + Ec;
        if (i < Eo) {
            int4 v0 = *(const int4*)(ei + i);
            int4 v1 = *(const int4*)(ei + Eo + i);
            float4 f0 = make_float4((float)v0.x, (float)v0.y, (float)v0.z, (float)v0.w);
            float4 f1 = make_float4((float)v1.x, (float)v1.y, (float)v1.z, (float)v1.w);
            *(float4*)(out_tei + i)      = f0;
            *(float4*)(out_tei + Et + i) = f1;
            *(float4*)(out_ei + i)       = f0;
            *(float4*)(out_ei + Eo + i)  = f1;
        }
        if (i < Ec) {
            int4 v0 = *(const int4*)(pei + i);
            int4 v1 = *(const int4*)(pei + Ec + i);
            float4 f0 = make_float4((float)v0.x, (float)v0.y, (float)v0.z, (float)v0.w);
            float4 f1 = make_float4((float)v1.x, (float)v1.y, (float)v1.z, (float)v1.w);
            *(float4*)(out_tei + Eo + i)      = f0;
            *(float4*)(out_tei + Et + Eo + i) = f1;
        }
        return;
    }

    // ---------------- edge dot role ----------------
    long long t = (long long)blockIdx.x * blockDim.x + threadIdx.x;
    long long e = t >> 3;
    int l = (int)(t & 7);
    if (e >= Eo) return;

    int i0 = ei[e];
    int i1 = ei[e + Eo];
    i0 = min(max(i0, 0), N - 1);
    i1 = min(max(i1, 0), N - 1);

    // one 16B chunk per row per thread; 8 lanes cover the 128B row exactly
    uint4 a = ((const uint4*)(g_reps_h + (size_t)i0 * 32))[l];
    uint4 b = ((const uint4*)(g_reps_h + (size_t)i1 * 32))[l];

    float acc = dot8h(a, b);

    acc += __shfl_xor_sync(0xffffffffu, acc, 4);
    acc += __shfl_xor_sync(0xffffffffu, acc, 2);
    acc += __shfl_xor_sync(0xffffffffu, acc, 1);

    if (l == 0) pw[e] = fmaxf(acc, 0.f);
}

extern "C" void kernel_launch(void* const* d_in, const int* in_sizes, int n_in,
                              void* d_out, int out_size)
{
    const float* feat = (const float*)d_in[0];
    const int*   ei   = (const int*)d_in[1];
    const int*   pei  = (const int*)d_in[2];
    const float* W1   = (const float*)d_in[3];
    const float* b1   = (const float*)d_in[4];
    const float* W2   = (const float*)d_in[5];
    const float* b2   = (const float*)d_in[6];
    float* out = (float*)d_out;

    const int N        = in_sizes[0] / 128;
    const long long Eo = in_sizes[1] / 2;
    const long long Ec = in_sizes[2] / 2;

    float* reps    = out;
    float* pw      = out + (size_t)N * 64;
    float* out_tei = pw + Eo;
    float* out_ei  = out_tei + 2 * (Eo + Ec);

    cudaFuncSetAttribute(mlp_mma_kernel,
                         cudaFuncAttributeMaxDynamicSharedMemorySize, SMEM_BYTES);

    int mlp_blocks = (N + NODES_PER_BLK - 1) / NODES_PER_BLK;
    mlp_mma_kernel<<<mlp_blocks, MLP_THREADS, SMEM_BYTES>>>(
        feat, W1, b1, W2, b2, reps, N);

    long long edge_threads = Eo * 8;
    int edge_blocks = (int)((edge_threads + 255) / 256);
    long long copy_items = (Eo > Ec ? Eo : Ec);
    int copy_blocks = (int)((copy_items + 256LL * 4 - 1) / (256LL * 4));

    edge_dot_plus_copy_kernel<<<edge_blocks + copy_blocks, 256>>>(
        ei, Eo, pw, N, edge_blocks, pei, Ec, out_tei, out_ei);
}

// round 9
// speedup vs baseline: 1.2973x; 1.2973x over previous
#include <cuda_runtime.h>
#include <cuda_fp16.h>
#include <cuda_bf16.h>
#include <cstdint>

// ---------------------------------------------------------------------------
// EstimateAdj:
//   h    = relu(features @ W1 + b1)   [N,128]->[N,64]
//   reps = h @ W2 + b2                [N,64]
//   pw[e] = relu(dot(reps[ei0[e]], reps[ei1[e]]))  e < Eo
// Output (float32 concat): reps | pw | total_edge_index | edge_index
//
// R9 = R8 with the split2 typo fixed (compile error only).
//  - edge: 8 lanes/edge (2 L1 wavefronts/edge, the floor) x 4 edges/thread
//  - index-copy role back in the MLP launch (hid fully there in R6)
//  - MLP B-fragments via ldmatrix.x4
// ---------------------------------------------------------------------------

#define MLP_THREADS 256
#define NODES_PER_BLK 128
#define N_MAX 100000

typedef unsigned int u32;

// fp16 shadow of reps (32 half2 per node = 128B/row) for the edge gather
__device__ __half2 g_reps_h[N_MAX * 32];

// smem layout (bytes):
//  Wt1h [64][136] bf16 : 0      .. 17408
//  Wt1l [64][136] bf16 : 17408  .. 34816
//  Wt2h [64][72]  bf16 : 34816  .. 44032
//  Wt2l [64][72]  bf16 : 44032  .. 53248
//  b1s  [64] f32       : 53248  .. 53504
//  b2s  [64] f32       : 53504  .. 53760
#define SMEM_BYTES 53760
#define W1_STRIDE 136   // elements; 68 words/row -> ldmatrix rows hit 4r%32 -> conflict-free
#define W2_STRIDE 72    // elements; 36 words/row -> same

__device__ __forceinline__ void mma_bf16(float* c, const u32* a, u32 b0, u32 b1) {
    asm volatile(
        "mma.sync.aligned.m16n8k16.row.col.f32.bf16.bf16.f32 "
        "{%0,%1,%2,%3}, {%4,%5,%6,%7}, {%8,%9}, {%0,%1,%2,%3};"
        : "+f"(c[0]), "+f"(c[1]), "+f"(c[2]), "+f"(c[3])
        : "r"(a[0]), "r"(a[1]), "r"(a[2]), "r"(a[3]), "r"(b0), "r"(b1));
}

__device__ __forceinline__ void ldsm_x4(u32* d, u32 saddr) {
    asm volatile(
        "ldmatrix.sync.aligned.m8n8.x4.shared.b16 {%0,%1,%2,%3}, [%4];"
        : "=r"(d[0]), "=r"(d[1]), "=r"(d[2]), "=r"(d[3]) : "r"(saddr));
}

// split (x,y) into bf16 hi pair + bf16 residual pair (packed, x in low half)
__device__ __forceinline__ void split2(float x, float y, u32& hi, u32& lo) {
    __nv_bfloat16 bx = __float2bfloat16(x), by = __float2bfloat16(y);
    hi = ((u32)__bfloat16_as_ushort(by) << 16) | (u32)__bfloat16_as_ushort(bx);
    float rx = x - __bfloat162float(bx);
    float ry = y - __bfloat162float(by);
    __nv_bfloat16 cx = __float2bfloat16(rx);
    __nv_bfloat16 cy = __float2bfloat16(ry);
    lo = ((u32)__bfloat16_as_ushort(cy) << 16) | (u32)__bfloat16_as_ushort(cx);
}

// MMA MLP + (role-split) index copy.
__global__ void __launch_bounds__(MLP_THREADS)
mlp_mma_kernel(const float* __restrict__ feat,
               const float* __restrict__ W1, const float* __restrict__ b1,
               const float* __restrict__ W2, const float* __restrict__ b2,
               float* __restrict__ reps, int N, int mlp_blocks,
               const int* __restrict__ ei, const int* __restrict__ pei,
               long long Eo, long long Ec,
               float* __restrict__ out_tei, float* __restrict__ out_ei)
{
    const int tx = threadIdx.x;

    if (blockIdx.x >= mlp_blocks) {
        // ---------------- index copy role (vectorized x4) ----------------
        long long i = ((long long)(blockIdx.x - mlp_blocks) * MLP_THREADS + tx) * 4;
        long long Et = Eo + Ec;
        if (i < Eo) {
            int4 v0 = *(const int4*)(ei + i);
            int4 v1 = *(const int4*)(ei + Eo + i);
            float4 f0 = make_float4((float)v0.x, (float)v0.y, (float)v0.z, (float)v0.w);
            float4 f1 = make_float4((float)v1.x, (float)v1.y, (float)v1.z, (float)v1.w);
            *(float4*)(out_tei + i)      = f0;
            *(float4*)(out_tei + Et + i) = f1;
            *(float4*)(out_ei + i)       = f0;
            *(float4*)(out_ei + Eo + i)  = f1;
        }
        if (i < Ec) {
            int4 v0 = *(const int4*)(pei + i);
            int4 v1 = *(const int4*)(pei + Ec + i);
            float4 f0 = make_float4((float)v0.x, (float)v0.y, (float)v0.z, (float)v0.w);
            float4 f1 = make_float4((float)v1.x, (float)v1.y, (float)v1.z, (float)v1.w);
            *(float4*)(out_tei + Eo + i)      = f0;
            *(float4*)(out_tei + Et + Eo + i) = f1;
        }
        return;
    }

    // ---------------- MLP role ----------------
    extern __shared__ char smc[];
    __nv_bfloat16* Wt1h = (__nv_bfloat16*)(smc);
    __nv_bfloat16* Wt1l = (__nv_bfloat16*)(smc + 17408);
    __nv_bfloat16* Wt2h = (__nv_bfloat16*)(smc + 34816);
    __nv_bfloat16* Wt2l = (__nv_bfloat16*)(smc + 44032);
    float* b1s = (float*)(smc + 53248);
    float* b2s = (float*)(smc + 53504);

    // Prologue: split W1, W2 to transposed bf16 hi/lo planes.
    for (int idx = tx; idx < 128 * 64; idx += MLP_THREADS) {
        int k = idx >> 6, n = idx & 63;
        float w = W1[idx];
        __nv_bfloat16 hi = __float2bfloat16(w);
        Wt1h[n * W1_STRIDE + k] = hi;
        Wt1l[n * W1_STRIDE + k] = __float2bfloat16(w - __bfloat162float(hi));
    }
    for (int idx = tx; idx < 64 * 64; idx += MLP_THREADS) {
        int k = idx >> 6, n = idx & 63;
        float w = W2[idx];
        __nv_bfloat16 hi = __float2bfloat16(w);
        Wt2h[n * W2_STRIDE + k] = hi;
        Wt2l[n * W2_STRIDE + k] = __float2bfloat16(w - __bfloat162float(hi));
    }
    if (tx < 64) { b1s[tx] = b1[tx]; b2s[tx] = b2[tx]; }
    __syncthreads();

    const int warp = tx >> 5, lane = tx & 31;
    const int g = lane >> 2, t = lane & 3;
    const int r0 = blockIdx.x * NODES_PER_BLK + warp * 16 + g;
    const int r1 = r0 + 8;
    const bool v0 = r0 < N, v1 = r1 < N;
    const float* f0p = feat + (size_t)(v0 ? r0 : 0) * 128 + t * 2;
    const float* f1p = feat + (size_t)(v1 ? r1 : 0) * 128 + t * 2;

    // ldmatrix per-lane offsets: lane>>3 selects (n-half, k-half):
    //   0:(n0,k0) 1:(n0,k0+8) 2:(n0+8,k0) 3:(n0+8,k0+8); row-in-tile = lane&7.
    const int n_part = (lane & 7) + ((lane & 16) ? 8 : 0);
    const int k_part = (lane & 8) ? 8 : 0;
    const u32 sw1h = (u32)__cvta_generic_to_shared(Wt1h) + (n_part * W1_STRIDE + k_part) * 2;
    const u32 sw1l = (u32)__cvta_generic_to_shared(Wt1l) + (n_part * W1_STRIDE + k_part) * 2;
    const u32 sw2h = (u32)__cvta_generic_to_shared(Wt2h) + (n_part * W2_STRIDE + k_part) * 2;
    const u32 sw2l = (u32)__cvta_generic_to_shared(Wt2l) + (n_part * W2_STRIDE + k_part) * 2;

    // ---- GEMM1: C[8 n-tiles][4] over K=128 (8 k-steps), 3-pass bf16 ----
    float C[8][4];
    #pragma unroll
    for (int n = 0; n < 8; n++)
        #pragma unroll
        for (int i = 0; i < 4; i++) C[n][i] = 0.f;

    #pragma unroll 2
    for (int kt = 0; kt < 8; kt++) {
        float2 x00 = v0 ? *(const float2*)(f0p + kt * 16)     : make_float2(0.f, 0.f);
        float2 x01 = v0 ? *(const float2*)(f0p + kt * 16 + 8) : make_float2(0.f, 0.f);
        float2 x10 = v1 ? *(const float2*)(f1p + kt * 16)     : make_float2(0.f, 0.f);
        float2 x11 = v1 ? *(const float2*)(f1p + kt * 16 + 8) : make_float2(0.f, 0.f);
        u32 ah[4], al[4];
        split2(x00.x, x00.y, ah[0], al[0]);
        split2(x10.x, x10.y, ah[1], al[1]);
        split2(x01.x, x01.y, ah[2], al[2]);
        split2(x11.x, x11.y, ah[3], al[3]);

        #pragma unroll
        for (int np = 0; np < 4; np++) {   // pair of n-tiles (2np, 2np+1)
            u32 off = (u32)((np * 16 * W1_STRIDE + kt * 16) * 2);
            u32 bh[4], bl[4];
            ldsm_x4(bh, sw1h + off);
            ldsm_x4(bl, sw1l + off);
            mma_bf16(C[2 * np],     ah, bh[0], bh[1]);
            mma_bf16(C[2 * np],     ah, bl[0], bl[1]);
            mma_bf16(C[2 * np],     al, bh[0], bh[1]);
            mma_bf16(C[2 * np + 1], ah, bh[2], bh[3]);
            mma_bf16(C[2 * np + 1], ah, bl[2], bl[3]);
            mma_bf16(C[2 * np + 1], al, bh[2], bh[3]);
        }
    }

    // bias + relu -> h (registers), then split into GEMM2 A-frags.
    #pragma unroll
    for (int n = 0; n < 8; n++) {
        float bb0 = b1s[n * 8 + t * 2];
        float bb1 = b1s[n * 8 + t * 2 + 1];
        C[n][0] = fmaxf(C[n][0] + bb0, 0.f);
        C[n][1] = fmaxf(C[n][1] + bb1, 0.f);
        C[n][2] = fmaxf(C[n][2] + bb0, 0.f);
        C[n][3] = fmaxf(C[n][3] + bb1, 0.f);
    }

    u32 a2h[4][4], a2l[4][4];
    #pragma unroll
    for (int kt = 0; kt < 4; kt++) {
        split2(C[2 * kt][0],     C[2 * kt][1],     a2h[kt][0], a2l[kt][0]);
        split2(C[2 * kt][2],     C[2 * kt][3],     a2h[kt][1], a2l[kt][1]);
        split2(C[2 * kt + 1][0], C[2 * kt + 1][1], a2h[kt][2], a2l[kt][2]);
        split2(C[2 * kt + 1][2], C[2 * kt + 1][3], a2h[kt][3], a2l[kt][3]);
    }

    // ---- GEMM2: D[8][4] over K=64 (4 k-steps), 3-pass bf16 ----
    float D[8][4];
    #pragma unroll
    for (int n = 0; n < 8; n++)
        #pragma unroll
        for (int i = 0; i < 4; i++) D[n][i] = 0.f;

    #pragma unroll
    for (int kt = 0; kt < 4; kt++) {
        #pragma unroll
        for (int np = 0; np < 4; np++) {
            u32 off = (u32)((np * 16 * W2_STRIDE + kt * 16) * 2);
            u32 bh[4], bl[4];
            ldsm_x4(bh, sw2h + off);
            ldsm_x4(bl, sw2l + off);
            mma_bf16(D[2 * np],     a2h[kt], bh[0], bh[1]);
            mma_bf16(D[2 * np],     a2h[kt], bl[0], bl[1]);
            mma_bf16(D[2 * np],     a2l[kt], bh[0], bh[1]);
            mma_bf16(D[2 * np + 1], a2h[kt], bh[2], bh[3]);
            mma_bf16(D[2 * np + 1], a2h[kt], bl[2], bl[3]);
            mma_bf16(D[2 * np + 1], a2l[kt], bh[2], bh[3]);
        }
    }

    // Epilogue: bias, store reps (fp32) + fp16 shadow.
    #pragma unroll
    for (int n = 0; n < 8; n++) {
        int c0 = n * 8 + t * 2;
        float bb0 = b2s[c0], bb1 = b2s[c0 + 1];
        if (v0) {
            float2 o = make_float2(D[n][0] + bb0, D[n][1] + bb1);
            *(float2*)(reps + (size_t)r0 * 64 + c0) = o;
            g_reps_h[(size_t)r0 * 32 + (c0 >> 1)] = __floats2half2_rn(o.x, o.y);
        }
        if (v1) {
            float2 o = make_float2(D[n][2] + bb0, D[n][3] + bb1);
            *(float2*)(reps + (size_t)r1 * 64 + c0) = o;
            g_reps_h[(size_t)r1 * 32 + (c0 >> 1)] = __floats2half2_rn(o.x, o.y);
        }
    }
}

__device__ __forceinline__ float dot8h(uint4 a, uint4 b) {
    const __half2* pa = (const __half2*)&a;
    const __half2* pb = (const __half2*)&b;
    float acc = 0.f;
    #pragma unroll
    for (int j = 0; j < 4; j++) {
        float2 x = __half22float2(pa[j]);
        float2 y = __half22float2(pb[j]);
        acc = fmaf(x.x, y.x, acc);
        acc = fmaf(x.y, y.y, acc);
    }
    return acc;
}

// Edge dots: 8 lanes/edge (1 LDG.128 per row -> 2 wavefronts/edge),
// 4 edges per thread (8 gather loads in flight). Warp = 16 edges.
__global__ void __launch_bounds__(256)
edge_dot_kernel(const int* __restrict__ ei, long long Eo,
                float* __restrict__ pw, int N)
{
    const int lane = threadIdx.x & 31;
    const int sub = lane & 7;      // 16B chunk within the 128B row
    const int g = lane >> 3;       // edge slot within warp (0..3)
    long long warp_g = ((long long)blockIdx.x * blockDim.x + threadIdx.x) >> 5;
    long long ebase = warp_g * 16;
    if (ebase >= Eo) return;

    int i0[4], i1[4];
    #pragma unroll
    for (int j = 0; j < 4; j++) {
        long long e = ebase + j * 4 + g;
        int a = (e < Eo) ? ei[e] : 0;
        int b = (e < Eo) ? ei[e + Eo] : 0;
        i0[j] = min(max(a, 0), N - 1);
        i1[j] = min(max(b, 0), N - 1);
    }

    uint4 av[4], bv[4];
    #pragma unroll
    for (int j = 0; j < 4; j++) {
        av[j] = ((const uint4*)(g_reps_h + (size_t)i0[j] * 32))[sub];
        bv[j] = ((const uint4*)(g_reps_h + (size_t)i1[j] * 32))[sub];
    }

    float acc[4];
    #pragma unroll
    for (int j = 0; j < 4; j++) {
        acc[j] = dot8h(av[j], bv[j]);
        acc[j] += __shfl_xor_sync(0xffffffffu, acc[j], 4);
        acc[j] += __shfl_xor_sync(0xffffffffu, acc[j], 2);
        acc[j] += __shfl_xor_sync(0xffffffffu, acc[j], 1);
    }

    if (sub == 0) {
        #pragma unroll
        for (int j = 0; j < 4; j++) {
            long long e = ebase + j * 4 + g;
            if (e < Eo) pw[e] = fmaxf(acc[j], 0.f);
        }
    }
}

extern "C" void kernel_launch(void* const* d_in, const int* in_sizes, int n_in,
                              void* d_out, int out_size)
{
    const float* feat = (const float*)d_in[0];
    const int*   ei   = (const int*)d_in[1];
    const int*   pei  = (const int*)d_in[2];
    const float* W1   = (const float*)d_in[3];
    const float* b1   = (const float*)d_in[4];
    const float* W2   = (const float*)d_in[5];
    const float* b2   = (const float*)d_in[6];
    float* out = (float*)d_out;

    const int N        = in_sizes[0] / 128;
    const long long Eo = in_sizes[1] / 2;
    const long long Ec = in_sizes[2] / 2;

    float* reps    = out;
    float* pw      = out + (size_t)N * 64;
    float* out_tei = pw + Eo;
    float* out_ei  = out_tei + 2 * (Eo + Ec);

    cudaFuncSetAttribute(mlp_mma_kernel,
                         cudaFuncAttributeMaxDynamicSharedMemorySize, SMEM_BYTES);

    int mlp_blocks = (N + NODES_PER_BLK - 1) / NODES_PER_BLK;
    long long copy_items = (Eo > Ec ? Eo : Ec);
    int copy_blocks = (int)((copy_items + MLP_THREADS * 4 - 1) / (MLP_THREADS * 4));

    mlp_mma_kernel<<<mlp_blocks + copy_blocks, MLP_THREADS, SMEM_BYTES>>>(
        feat, W1, b1, W2, b2, reps, N, mlp_blocks,
        ei, pei, Eo, Ec, out_tei, out_ei);

    // warps of 16 edges each
    long long warps = (Eo + 15) / 16;
    long long threads = warps * 32;
    int edge_blocks = (int)((threads + 255) / 256);
    edge_dot_kernel<<<edge_blocks, 256>>>(ei, Eo, pw, N);
}

// round 10
// speedup vs baseline: 1.3644x; 1.0517x over previous
#include <cuda_runtime.h>
#include <cuda_fp16.h>
#include <cuda_bf16.h>
#include <cstdint>

// ---------------------------------------------------------------------------
// EstimateAdj:
//   h    = relu(features @ W1 + b1)   [N,128]->[N,64]
//   reps = h @ W2 + b2                [N,64]
//   pw[e] = relu(dot(reps[ei0[e]], reps[ei1[e]]))  e < Eo
// Output (float32 concat): reps | pw | total_edge_index | edge_index
//
// R10 vs R9 (82.7us):
//  - MLP: revert B-frag loads to direct LDS (R6 style, was faster than ldsm);
//    epilogue stages reps+shadow in smem (reusing dead weight regions) and
//    writes coalesced float4/uint4 -> ~5x fewer store wavefronts
//  - edge: int4 index loads (lane owns 4 consecutive edges), float4 pw store
// ---------------------------------------------------------------------------

#define MLP_THREADS 256
#define NODES_PER_BLK 128
#define N_MAX 100000

typedef unsigned int u32;

// fp16 shadow of reps (32 half2 per node = 128B/row) for the edge gather
__device__ __half2 g_reps_h[N_MAX * 32];

// smem layout (bytes):
//  Wt1h [64][136] bf16 : 0      .. 17408   } GEMM phase
//  Wt1l [64][136] bf16 : 17408  .. 34816   }
//  Wt2h [64][72]  bf16 : 34816  .. 44032   }
//  Wt2l [64][72]  bf16 : 44032  .. 53248   }
//  rstage [128][68] f32   : 0     .. 34816  } epilogue phase (reuses Wt1)
//  hstage [128][36] half2 : 34816 .. 53248  } epilogue phase (reuses Wt2)
//  b1s  [64] f32       : 53248  .. 53504   (never overwritten)
//  b2s  [64] f32       : 53504  .. 53760
#define SMEM_BYTES 53760
#define W1_STRIDE 136   // elements; 68 words/row -> (68*(8n+g)+t)%32 = (4g+t)%32
#define W2_STRIDE 72    // elements; 36 words/row -> same property
#define RSTAGE_STRIDE 68   // floats; 68%32=4 -> row phase 4r, conflict-free
#define HSTAGE_STRIDE 36   // half2 words; 36%32=4 -> same

__device__ __forceinline__ void mma_bf16(float* c, const u32* a, u32 b0, u32 b1) {
    asm volatile(
        "mma.sync.aligned.m16n8k16.row.col.f32.bf16.bf16.f32 "
        "{%0,%1,%2,%3}, {%4,%5,%6,%7}, {%8,%9}, {%0,%1,%2,%3};"
        : "+f"(c[0]), "+f"(c[1]), "+f"(c[2]), "+f"(c[3])
        : "r"(a[0]), "r"(a[1]), "r"(a[2]), "r"(a[3]), "r"(b0), "r"(b1));
}

// split (x,y) into bf16 hi pair + bf16 residual pair (packed, x in low half)
__device__ __forceinline__ void split2(float x, float y, u32& hi, u32& lo) {
    __nv_bfloat16 bx = __float2bfloat16(x), by = __float2bfloat16(y);
    hi = ((u32)__bfloat16_as_ushort(by) << 16) | (u32)__bfloat16_as_ushort(bx);
    float rx = x - __bfloat162float(bx);
    float ry = y - __bfloat162float(by);
    __nv_bfloat16 cx = __float2bfloat16(rx);
    __nv_bfloat16 cy = __float2bfloat16(ry);
    lo = ((u32)__bfloat16_as_ushort(cy) << 16) | (u32)__bfloat16_as_ushort(cx);
}

// MMA MLP + (role-split) index copy.
__global__ void __launch_bounds__(MLP_THREADS)
mlp_mma_kernel(const float* __restrict__ feat,
               const float* __restrict__ W1, const float* __restrict__ b1,
               const float* __restrict__ W2, const float* __restrict__ b2,
               float* __restrict__ reps, int N, int mlp_blocks,
               const int* __restrict__ ei, const int* __restrict__ pei,
               long long Eo, long long Ec,
               float* __restrict__ out_tei, float* __restrict__ out_ei)
{
    const int tx = threadIdx.x;

    if (blockIdx.x >= mlp_blocks) {
        // ---------------- index copy role (vectorized x4) ----------------
        long long i = ((long long)(blockIdx.x - mlp_blocks) * MLP_THREADS + tx) * 4;
        long long Et = Eo + Ec;
        if (i < Eo) {
            int4 v0 = *(const int4*)(ei + i);
            int4 v1 = *(const int4*)(ei + Eo + i);
            float4 f0 = make_float4((float)v0.x, (float)v0.y, (float)v0.z, (float)v0.w);
            float4 f1 = make_float4((float)v1.x, (float)v1.y, (float)v1.z, (float)v1.w);
            *(float4*)(out_tei + i)      = f0;
            *(float4*)(out_tei + Et + i) = f1;
            *(float4*)(out_ei + i)       = f0;
            *(float4*)(out_ei + Eo + i)  = f1;
        }
        if (i < Ec) {
            int4 v0 = *(const int4*)(pei + i);
            int4 v1 = *(const int4*)(pei + Ec + i);
            float4 f0 = make_float4((float)v0.x, (float)v0.y, (float)v0.z, (float)v0.w);
            float4 f1 = make_float4((float)v1.x, (float)v1.y, (float)v1.z, (float)v1.w);
            *(float4*)(out_tei + Eo + i)      = f0;
            *(float4*)(out_tei + Et + Eo + i) = f1;
        }
        return;
    }

    // ---------------- MLP role ----------------
    extern __shared__ char smc[];
    __nv_bfloat16* Wt1h = (__nv_bfloat16*)(smc);
    __nv_bfloat16* Wt1l = (__nv_bfloat16*)(smc + 17408);
    __nv_bfloat16* Wt2h = (__nv_bfloat16*)(smc + 34816);
    __nv_bfloat16* Wt2l = (__nv_bfloat16*)(smc + 44032);
    float* b1s = (float*)(smc + 53248);
    float* b2s = (float*)(smc + 53504);

    // Prologue: split W1, W2 to transposed bf16 hi/lo planes.
    for (int idx = tx; idx < 128 * 64; idx += MLP_THREADS) {
        int k = idx >> 6, n = idx & 63;
        float w = W1[idx];
        __nv_bfloat16 hi = __float2bfloat16(w);
        Wt1h[n * W1_STRIDE + k] = hi;
        Wt1l[n * W1_STRIDE + k] = __float2bfloat16(w - __bfloat162float(hi));
    }
    for (int idx = tx; idx < 64 * 64; idx += MLP_THREADS) {
        int k = idx >> 6, n = idx & 63;
        float w = W2[idx];
        __nv_bfloat16 hi = __float2bfloat16(w);
        Wt2h[n * W2_STRIDE + k] = hi;
        Wt2l[n * W2_STRIDE + k] = __float2bfloat16(w - __bfloat162float(hi));
    }
    if (tx < 64) { b1s[tx] = b1[tx]; b2s[tx] = b2[tx]; }
    __syncthreads();

    const int warp = tx >> 5, lane = tx & 31;
    const int g = lane >> 2, t = lane & 3;
    const int r0 = blockIdx.x * NODES_PER_BLK + warp * 16 + g;
    const int r1 = r0 + 8;
    const bool v0 = r0 < N, v1 = r1 < N;
    const float* f0p = feat + (size_t)(v0 ? r0 : 0) * 128 + t * 2;
    const float* f1p = feat + (size_t)(v1 ? r1 : 0) * 128 + t * 2;

    // ---- GEMM1: C[8 n-tiles][4] over K=128 (8 k-steps), 3-pass bf16 ----
    float C[8][4];
    #pragma unroll
    for (int n = 0; n < 8; n++)
        #pragma unroll
        for (int i = 0; i < 4; i++) C[n][i] = 0.f;

    #pragma unroll 2
    for (int kt = 0; kt < 8; kt++) {
        float2 x00 = v0 ? *(const float2*)(f0p + kt * 16)     : make_float2(0.f, 0.f);
        float2 x01 = v0 ? *(const float2*)(f0p + kt * 16 + 8) : make_float2(0.f, 0.f);
        float2 x10 = v1 ? *(const float2*)(f1p + kt * 16)     : make_float2(0.f, 0.f);
        float2 x11 = v1 ? *(const float2*)(f1p + kt * 16 + 8) : make_float2(0.f, 0.f);
        u32 ah[4], al[4];
        split2(x00.x, x00.y, ah[0], al[0]);
        split2(x10.x, x10.y, ah[1], al[1]);
        split2(x01.x, x01.y, ah[2], al[2]);
        split2(x11.x, x11.y, ah[3], al[3]);

        const int kb = kt * 16 + t * 2;
        #pragma unroll
        for (int n = 0; n < 8; n++) {
            const __nv_bfloat16* wh = Wt1h + (n * 8 + g) * W1_STRIDE + kb;
            const __nv_bfloat16* wl = Wt1l + (n * 8 + g) * W1_STRIDE + kb;
            u32 bh0 = *(const u32*)(wh);
            u32 bh1 = *(const u32*)(wh + 8);
            u32 bl0 = *(const u32*)(wl);
            u32 bl1 = *(const u32*)(wl + 8);
            mma_bf16(C[n], ah, bh0, bh1);
            mma_bf16(C[n], ah, bl0, bl1);
            mma_bf16(C[n], al, bh0, bh1);
        }
    }

    // bias + relu -> h (registers), then split into GEMM2 A-frags.
    #pragma unroll
    for (int n = 0; n < 8; n++) {
        float bb0 = b1s[n * 8 + t * 2];
        float bb1 = b1s[n * 8 + t * 2 + 1];
        C[n][0] = fmaxf(C[n][0] + bb0, 0.f);
        C[n][1] = fmaxf(C[n][1] + bb1, 0.f);
        C[n][2] = fmaxf(C[n][2] + bb0, 0.f);
        C[n][3] = fmaxf(C[n][3] + bb1, 0.f);
    }

    u32 a2h[4][4], a2l[4][4];
    #pragma unroll
    for (int kt = 0; kt < 4; kt++) {
        split2(C[2 * kt][0],     C[2 * kt][1],     a2h[kt][0], a2l[kt][0]);
        split2(C[2 * kt][2],     C[2 * kt][3],     a2h[kt][1], a2l[kt][1]);
        split2(C[2 * kt + 1][0], C[2 * kt + 1][1], a2h[kt][2], a2l[kt][2]);
        split2(C[2 * kt + 1][2], C[2 * kt + 1][3], a2h[kt][3], a2l[kt][3]);
    }

    // ---- GEMM2: D[8][4] over K=64 (4 k-steps), 3-pass bf16 ----
    float D[8][4];
    #pragma unroll
    for (int n = 0; n < 8; n++)
        #pragma unroll
        for (int i = 0; i < 4; i++) D[n][i] = 0.f;

    #pragma unroll
    for (int kt = 0; kt < 4; kt++) {
        const int kb = kt * 16 + t * 2;
        #pragma unroll
        for (int n = 0; n < 8; n++) {
            const __nv_bfloat16* wh = Wt2h + (n * 8 + g) * W2_STRIDE + kb;
            const __nv_bfloat16* wl = Wt2l + (n * 8 + g) * W2_STRIDE + kb;
            u32 bh0 = *(const u32*)(wh);
            u32 bh1 = *(const u32*)(wh + 8);
            u32 bl0 = *(const u32*)(wl);
            u32 bl1 = *(const u32*)(wl + 8);
            mma_bf16(D[n], a2h[kt], bh0, bh1);
            mma_bf16(D[n], a2h[kt], bl0, bl1);
            mma_bf16(D[n], a2l[kt], bh0, bh1);
        }
    }

    // ---- Epilogue: stage in smem (weight regions now dead), then coalesce ----
    __syncthreads();   // all warps done reading Wt1/Wt2
    float*   rstage = (float*)smc;                 // [128][68]
    __half2* hstage = (__half2*)(smc + 34816);     // [128][36]

    const int lr0 = warp * 16 + g;
    const int lr1 = lr0 + 8;
    #pragma unroll
    for (int n = 0; n < 8; n++) {
        int c0 = n * 8 + t * 2;
        float bb0 = b2s[c0], bb1 = b2s[c0 + 1];
        float2 o0 = make_float2(D[n][0] + bb0, D[n][1] + bb1);
        float2 o1 = make_float2(D[n][2] + bb0, D[n][3] + bb1);
        rstage[lr0 * RSTAGE_STRIDE + c0]     = o0.x;
        rstage[lr0 * RSTAGE_STRIDE + c0 + 1] = o0.y;
        rstage[lr1 * RSTAGE_STRIDE + c0]     = o1.x;
        rstage[lr1 * RSTAGE_STRIDE + c0 + 1] = o1.y;
        hstage[lr0 * HSTAGE_STRIDE + (c0 >> 1)] = __floats2half2_rn(o0.x, o0.y);
        hstage[lr1 * HSTAGE_STRIDE + (c0 >> 1)] = __floats2half2_rn(o1.x, o1.y);
    }
    __syncthreads();

    const int base_row = blockIdx.x * NODES_PER_BLK;
    // reps: 128 rows x 16 float4, coalesced
    for (int i = tx; i < 128 * 16; i += MLP_THREADS) {
        int row = i >> 4, c = i & 15;
        int grow = base_row + row;
        if (grow < N) {
            const float* s = rstage + row * RSTAGE_STRIDE + c * 4;
            float4 v = make_float4(s[0], s[1], s[2], s[3]);
            *(float4*)(reps + (size_t)grow * 64 + c * 4) = v;
        }
    }
    // shadow: 128 rows x 8 uint4, coalesced
    for (int i = tx; i < 128 * 8; i += MLP_THREADS) {
        int row = i >> 3, c = i & 7;
        int grow = base_row + row;
        if (grow < N) {
            uint4 v = *(const uint4*)(hstage + row * HSTAGE_STRIDE + c * 4);
            *(uint4*)(g_reps_h + (size_t)grow * 32 + c * 4) = v;
        }
    }
}

__device__ __forceinline__ float dot8h(uint4 a, uint4 b) {
    const __half2* pa = (const __half2*)&a;
    const __half2* pb = (const __half2*)&b;
    float acc = 0.f;
    #pragma unroll
    for (int j = 0; j < 4; j++) {
        float2 x = __half22float2(pa[j]);
        float2 y = __half22float2(pb[j]);
        acc = fmaf(x.x, y.x, acc);
        acc = fmaf(x.y, y.y, acc);
    }
    return acc;
}

// Edge dots: 8 lanes/edge, 4 consecutive edges per lane-group -> int4 index
// loads and float4 pw stores. Warp = 16 edges.
__global__ void __launch_bounds__(256)
edge_dot_kernel(const int* __restrict__ ei, long long Eo,
                float* __restrict__ pw, int N)
{
    const int lane = threadIdx.x & 31;
    const int sub = lane & 7;      // 16B chunk within the 128B row
    const int g = lane >> 3;       // edge group within warp (0..3)
    long long warp_g = ((long long)blockIdx.x * blockDim.x + threadIdx.x) >> 5;
    long long ebase = warp_g * 16;
    if (ebase >= Eo) return;

    const bool full = (ebase + 16 <= Eo) && ((Eo & 3) == 0);
    int i0[4], i1[4];
    if (full) {
        int4 va = *(const int4*)(ei + ebase + g * 4);
        int4 vb = *(const int4*)(ei + Eo + ebase + g * 4);
        i0[0] = va.x; i0[1] = va.y; i0[2] = va.z; i0[3] = va.w;
        i1[0] = vb.x; i1[1] = vb.y; i1[2] = vb.z; i1[3] = vb.w;
    } else {
        #pragma unroll
        for (int j = 0; j < 4; j++) {
            long long e = ebase + g * 4 + j;
            i0[j] = (e < Eo) ? ei[e] : 0;
            i1[j] = (e < Eo) ? ei[e + Eo] : 0;
        }
    }
    #pragma unroll
    for (int j = 0; j < 4; j++) {
        i0[j] = min(max(i0[j], 0), N - 1);
        i1[j] = min(max(i1[j], 0), N - 1);
    }

    uint4 av[4], bv[4];
    #pragma unroll
    for (int j = 0; j < 4; j++) {
        av[j] = ((const uint4*)(g_reps_h + (size_t)i0[j] * 32))[sub];
        bv[j] = ((const uint4*)(g_reps_h + (size_t)i1[j] * 32))[sub];
    }

    float acc[4];
    #pragma unroll
    for (int j = 0; j < 4; j++) {
        acc[j] = dot8h(av[j], bv[j]);
        acc[j] += __shfl_xor_sync(0xffffffffu, acc[j], 4);
        acc[j] += __shfl_xor_sync(0xffffffffu, acc[j], 2);
        acc[j] += __shfl_xor_sync(0xffffffffu, acc[j], 1);
        acc[j] = fmaxf(acc[j], 0.f);
    }

    if (sub == 0) {
        if (full) {
            *(float4*)(pw + ebase + g * 4) = make_float4(acc[0], acc[1], acc[2], acc[3]);
        } else {
            #pragma unroll
            for (int j = 0; j < 4; j++) {
                long long e = ebase + g * 4 + j;
                if (e < Eo) pw[e] = acc[j];
            }
        }
    }
}

extern "C" void kernel_launch(void* const* d_in, const int* in_sizes, int n_in,
                              void* d_out, int out_size)
{
    const float* feat = (const float*)d_in[0];
    const int*   ei   = (const int*)d_in[1];
    const int*   pei  = (const int*)d_in[2];
    const float* W1   = (const float*)d_in[3];
    const float* b1   = (const float*)d_in[4];
    const float* W2   = (const float*)d_in[5];
    const float* b2   = (const float*)d_in[6];
    float* out = (float*)d_out;

    const int N        = in_sizes[0] / 128;
    const long long Eo = in_sizes[1] / 2;
    const long long Ec = in_sizes[2] / 2;

    float* reps    = out;
    float* pw      = out + (size_t)N * 64;
    float* out_tei = pw + Eo;
    float* out_ei  = out_tei + 2 * (Eo + Ec);

    cudaFuncSetAttribute(mlp_mma_kernel,
                         cudaFuncAttributeMaxDynamicSharedMemorySize, SMEM_BYTES);

    int mlp_blocks = (N + NODES_PER_BLK - 1) / NODES_PER_BLK;
    long long copy_items = (Eo > Ec ? Eo : Ec);
    int copy_blocks = (int)((copy_items + MLP_THREADS * 4 - 1) / (MLP_THREADS * 4));

    mlp_mma_kernel<<<mlp_blocks + copy_blocks, MLP_THREADS, SMEM_BYTES>>>(
        feat, W1, b1, W2, b2, reps, N, mlp_blocks,
        ei, pei, Eo, Ec, out_tei, out_ei);

    // warps of 16 edges each
    long long warps = (Eo + 15) / 16;
    long long threads = warps * 32;
    int edge_blocks = (int)((threads + 255) / 256);
    edge_dot_kernel<<<edge_blocks, 256>>>(ei, Eo, pw, N);
}

// round 11
// speedup vs baseline: 1.4062x; 1.0306x over previous
#include <cuda_runtime.h>
#include <cuda_fp16.h>
#include <cuda_bf16.h>
#include <cstdint>

// ---------------------------------------------------------------------------
// EstimateAdj:
//   h    = relu(features @ W1 + b1)   [N,128]->[N,64]
//   reps = h @ W2 + b2                [N,64]
//   pw[e] = relu(dot(reps[ei0[e]], reps[ei1[e]]))  e < Eo
// Output (float32 concat): reps | pw | total_edge_index | edge_index
//
// R11 = best-of: R10 MLP (smem-staged coalesced epilogue, 43.0us measured)
//     + R9 edge kernel verbatim (8 lanes/edge x 4 edges/thread, scalar index
//       loads, 32 regs, occ 87%, 31.9us measured).
// R10's int4/float4 edge variant regressed (regs 42, occ 54%) -> reverted.
// ---------------------------------------------------------------------------

#define MLP_THREADS 256
#define NODES_PER_BLK 128
#define N_MAX 100000

typedef unsigned int u32;

// fp16 shadow of reps (32 half2 per node = 128B/row) for the edge gather
__device__ __half2 g_reps_h[N_MAX * 32];

// smem layout (bytes):
//  Wt1h [64][136] bf16 : 0      .. 17408   } GEMM phase
//  Wt1l [64][136] bf16 : 17408  .. 34816   }
//  Wt2h [64][72]  bf16 : 34816  .. 44032   }
//  Wt2l [64][72]  bf16 : 44032  .. 53248   }
//  rstage [128][68] f32   : 0     .. 34816  } epilogue phase (reuses Wt1)
//  hstage [128][36] half2 : 34816 .. 53248  } epilogue phase (reuses Wt2)
//  b1s  [64] f32       : 53248  .. 53504   (never overwritten)
//  b2s  [64] f32       : 53504  .. 53760
#define SMEM_BYTES 53760
#define W1_STRIDE 136   // elements; 68 words/row -> (68*(8n+g)+t)%32 = (4g+t)%32
#define W2_STRIDE 72    // elements; 36 words/row -> same property
#define RSTAGE_STRIDE 68   // floats; 68%32=4 -> conflict-free
#define HSTAGE_STRIDE 36   // half2 words; 36%32=4 -> same

__device__ __forceinline__ void mma_bf16(float* c, const u32* a, u32 b0, u32 b1) {
    asm volatile(
        "mma.sync.aligned.m16n8k16.row.col.f32.bf16.bf16.f32 "
        "{%0,%1,%2,%3}, {%4,%5,%6,%7}, {%8,%9}, {%0,%1,%2,%3};"
        : "+f"(c[0]), "+f"(c[1]), "+f"(c[2]), "+f"(c[3])
        : "r"(a[0]), "r"(a[1]), "r"(a[2]), "r"(a[3]), "r"(b0), "r"(b1));
}

// split (x,y) into bf16 hi pair + bf16 residual pair (packed, x in low half)
__device__ __forceinline__ void split2(float x, float y, u32& hi, u32& lo) {
    __nv_bfloat16 bx = __float2bfloat16(x), by = __float2bfloat16(y);
    hi = ((u32)__bfloat16_as_ushort(by) << 16) | (u32)__bfloat16_as_ushort(bx);
    float rx = x - __bfloat162float(bx);
    float ry = y - __bfloat162float(by);
    __nv_bfloat16 cx = __float2bfloat16(rx);
    __nv_bfloat16 cy = __float2bfloat16(ry);
    lo = ((u32)__bfloat16_as_ushort(cy) << 16) | (u32)__bfloat16_as_ushort(cx);
}

// MMA MLP + (role-split) index copy.
__global__ void __launch_bounds__(MLP_THREADS)
mlp_mma_kernel(const float* __restrict__ feat,
               const float* __restrict__ W1, const float* __restrict__ b1,
               const float* __restrict__ W2, const float* __restrict__ b2,
               float* __restrict__ reps, int N, int mlp_blocks,
               const int* __restrict__ ei, const int* __restrict__ pei,
               long long Eo, long long Ec,
               float* __restrict__ out_tei, float* __restrict__ out_ei)
{
    const int tx = threadIdx.x;

    if (blockIdx.x >= mlp_blocks) {
        // ---------------- index copy role (vectorized x4) ----------------
        long long i = ((long long)(blockIdx.x - mlp_blocks) * MLP_THREADS + tx) * 4;
        long long Et = Eo + Ec;
        if (i < Eo) {
            int4 v0 = *(const int4*)(ei + i);
            int4 v1 = *(const int4*)(ei + Eo + i);
            float4 f0 = make_float4((float)v0.x, (float)v0.y, (float)v0.z, (float)v0.w);
            float4 f1 = make_float4((float)v1.x, (float)v1.y, (float)v1.z, (float)v1.w);
            *(float4*)(out_tei + i)      = f0;
            *(float4*)(out_tei + Et + i) = f1;
            *(float4*)(out_ei + i)       = f0;
            *(float4*)(out_ei + Eo + i)  = f1;
        }
        if (i < Ec) {
            int4 v0 = *(const int4*)(pei + i);
            int4 v1 = *(const int4*)(pei + Ec + i);
            float4 f0 = make_float4((float)v0.x, (float)v0.y, (float)v0.z, (float)v0.w);
            float4 f1 = make_float4((float)v1.x, (float)v1.y, (float)v1.z, (float)v1.w);
            *(float4*)(out_tei + Eo + i)      = f0;
            *(float4*)(out_tei + Et + Eo + i) = f1;
        }
        return;
    }

    // ---------------- MLP role ----------------
    extern __shared__ char smc[];
    __nv_bfloat16* Wt1h = (__nv_bfloat16*)(smc);
    __nv_bfloat16* Wt1l = (__nv_bfloat16*)(smc + 17408);
    __nv_bfloat16* Wt2h = (__nv_bfloat16*)(smc + 34816);
    __nv_bfloat16* Wt2l = (__nv_bfloat16*)(smc + 44032);
    float* b1s = (float*)(smc + 53248);
    float* b2s = (float*)(smc + 53504);

    // Prologue: split W1, W2 to transposed bf16 hi/lo planes.
    for (int idx = tx; idx < 128 * 64; idx += MLP_THREADS) {
        int k = idx >> 6, n = idx & 63;
        float w = W1[idx];
        __nv_bfloat16 hi = __float2bfloat16(w);
        Wt1h[n * W1_STRIDE + k] = hi;
        Wt1l[n * W1_STRIDE + k] = __float2bfloat16(w - __bfloat162float(hi));
    }
    for (int idx = tx; idx < 64 * 64; idx += MLP_THREADS) {
        int k = idx >> 6, n = idx & 63;
        float w = W2[idx];
        __nv_bfloat16 hi = __float2bfloat16(w);
        Wt2h[n * W2_STRIDE + k] = hi;
        Wt2l[n * W2_STRIDE + k] = __float2bfloat16(w - __bfloat162float(hi));
    }
    if (tx < 64) { b1s[tx] = b1[tx]; b2s[tx] = b2[tx]; }
    __syncthreads();

    const int warp = tx >> 5, lane = tx & 31;
    const int g = lane >> 2, t = lane & 3;
    const int r0 = blockIdx.x * NODES_PER_BLK + warp * 16 + g;
    const int r1 = r0 + 8;
    const bool v0 = r0 < N, v1 = r1 < N;
    const float* f0p = feat + (size_t)(v0 ? r0 : 0) * 128 + t * 2;
    const float* f1p = feat + (size_t)(v1 ? r1 : 0) * 128 + t * 2;

    // ---- GEMM1: C[8 n-tiles][4] over K=128 (8 k-steps), 3-pass bf16 ----
    float C[8][4];
    #pragma unroll
    for (int n = 0; n < 8; n++)
        #pragma unroll
        for (int i = 0; i < 4; i++) C[n][i] = 0.f;

    #pragma unroll 2
    for (int kt = 0; kt < 8; kt++) {
        float2 x00 = v0 ? *(const float2*)(f0p + kt * 16)     : make_float2(0.f, 0.f);
        float2 x01 = v0 ? *(const float2*)(f0p + kt * 16 + 8) : make_float2(0.f, 0.f);
        float2 x10 = v1 ? *(const float2*)(f1p + kt * 16)     : make_float2(0.f, 0.f);
        float2 x11 = v1 ? *(const float2*)(f1p + kt * 16 + 8) : make_float2(0.f, 0.f);
        u32 ah[4], al[4];
        split2(x00.x, x00.y, ah[0], al[0]);
        split2(x10.x, x10.y, ah[1], al[1]);
        split2(x01.x, x01.y, ah[2], al[2]);
        split2(x11.x, x11.y, ah[3], al[3]);

        const int kb = kt * 16 + t * 2;
        #pragma unroll
        for (int n = 0; n < 8; n++) {
            const __nv_bfloat16* wh = Wt1h + (n * 8 + g) * W1_STRIDE + kb;
            const __nv_bfloat16* wl = Wt1l + (n * 8 + g) * W1_STRIDE + kb;
            u32 bh0 = *(const u32*)(wh);
            u32 bh1 = *(const u32*)(wh + 8);
            u32 bl0 = *(const u32*)(wl);
            u32 bl1 = *(const u32*)(wl + 8);
            mma_bf16(C[n], ah, bh0, bh1);
            mma_bf16(C[n], ah, bl0, bl1);
            mma_bf16(C[n], al, bh0, bh1);
        }
    }

    // bias + relu -> h (registers), then split into GEMM2 A-frags.
    #pragma unroll
    for (int n = 0; n < 8; n++) {
        float bb0 = b1s[n * 8 + t * 2];
        float bb1 = b1s[n * 8 + t * 2 + 1];
        C[n][0] = fmaxf(C[n][0] + bb0, 0.f);
        C[n][1] = fmaxf(C[n][1] + bb1, 0.f);
        C[n][2] = fmaxf(C[n][2] + bb0, 0.f);
        C[n][3] = fmaxf(C[n][3] + bb1, 0.f);
    }

    u32 a2h[4][4], a2l[4][4];
    #pragma unroll
    for (int kt = 0; kt < 4; kt++) {
        split2(C[2 * kt][0],     C[2 * kt][1],     a2h[kt][0], a2l[kt][0]);
        split2(C[2 * kt][2],     C[2 * kt][3],     a2h[kt][1], a2l[kt][1]);
        split2(C[2 * kt + 1][0], C[2 * kt + 1][1], a2h[kt][2], a2l[kt][2]);
        split2(C[2 * kt + 1][2], C[2 * kt + 1][3], a2h[kt][3], a2l[kt][3]);
    }

    // ---- GEMM2: D[8][4] over K=64 (4 k-steps), 3-pass bf16 ----
    float D[8][4];
    #pragma unroll
    for (int n = 0; n < 8; n++)
        #pragma unroll
        for (int i = 0; i < 4; i++) D[n][i] = 0.f;

    #pragma unroll
    for (int kt = 0; kt < 4; kt++) {
        const int kb = kt * 16 + t * 2;
        #pragma unroll
        for (int n = 0; n < 8; n++) {
            const __nv_bfloat16* wh = Wt2h + (n * 8 + g) * W2_STRIDE + kb;
            const __nv_bfloat16* wl = Wt2l + (n * 8 + g) * W2_STRIDE + kb;
            u32 bh0 = *(const u32*)(wh);
            u32 bh1 = *(const u32*)(wh + 8);
            u32 bl0 = *(const u32*)(wl);
            u32 bl1 = *(const u32*)(wl + 8);
            mma_bf16(D[n], a2h[kt], bh0, bh1);
            mma_bf16(D[n], a2h[kt], bl0, bl1);
            mma_bf16(D[n], a2l[kt], bh0, bh1);
        }
    }

    // ---- Epilogue: stage in smem (weight regions now dead), then coalesce ----
    __syncthreads();   // all warps done reading Wt1/Wt2
    float*   rstage = (float*)smc;                 // [128][68]
    __half2* hstage = (__half2*)(smc + 34816);     // [128][36]

    const int lr0 = warp * 16 + g;
    const int lr1 = lr0 + 8;
    #pragma unroll
    for (int n = 0; n < 8; n++) {
        int c0 = n * 8 + t * 2;
        float bb0 = b2s[c0], bb1 = b2s[c0 + 1];
        float2 o0 = make_float2(D[n][0] + bb0, D[n][1] + bb1);
        float2 o1 = make_float2(D[n][2] + bb0, D[n][3] + bb1);
        rstage[lr0 * RSTAGE_STRIDE + c0]     = o0.x;
        rstage[lr0 * RSTAGE_STRIDE + c0 + 1] = o0.y;
        rstage[lr1 * RSTAGE_STRIDE + c0]     = o1.x;
        rstage[lr1 * RSTAGE_STRIDE + c0 + 1] = o1.y;
        hstage[lr0 * HSTAGE_STRIDE + (c0 >> 1)] = __floats2half2_rn(o0.x, o0.y);
        hstage[lr1 * HSTAGE_STRIDE + (c0 >> 1)] = __floats2half2_rn(o1.x, o1.y);
    }
    __syncthreads();

    const int base_row = blockIdx.x * NODES_PER_BLK;
    // reps: 128 rows x 16 float4, coalesced
    for (int i = tx; i < 128 * 16; i += MLP_THREADS) {
        int row = i >> 4, c = i & 15;
        int grow = base_row + row;
        if (grow < N) {
            const float* s = rstage + row * RSTAGE_STRIDE + c * 4;
            float4 v = make_float4(s[0], s[1], s[2], s[3]);
            *(float4*)(reps + (size_t)grow * 64 + c * 4) = v;
        }
    }
    // shadow: 128 rows x 8 uint4, coalesced
    for (int i = tx; i < 128 * 8; i += MLP_THREADS) {
        int row = i >> 3, c = i & 7;
        int grow = base_row + row;
        if (grow < N) {
            uint4 v = *(const uint4*)(hstage + row * HSTAGE_STRIDE + c * 4);
            *(uint4*)(g_reps_h + (size_t)grow * 32 + c * 4) = v;
        }
    }
}

__device__ __forceinline__ float dot8h(uint4 a, uint4 b) {
    const __half2* pa = (const __half2*)&a;
    const __half2* pb = (const __half2*)&b;
    float acc = 0.f;
    #pragma unroll
    for (int j = 0; j < 4; j++) {
        float2 x = __half22float2(pa[j]);
        float2 y = __half22float2(pb[j]);
        acc = fmaf(x.x, y.x, acc);
        acc = fmaf(x.y, y.y, acc);
    }
    return acc;
}

// Edge dots (R9 version verbatim): 8 lanes/edge, 4 edges/thread.
__global__ void __launch_bounds__(256)
edge_dot_kernel(const int* __restrict__ ei, long long Eo,
                float* __restrict__ pw, int N)
{
    const int lane = threadIdx.x & 31;
    const int sub = lane & 7;      // 16B chunk within the 128B row
    const int g = lane >> 3;       // edge slot within warp (0..3)
    long long warp_g = ((long long)blockIdx.x * blockDim.x + threadIdx.x) >> 5;
    long long ebase = warp_g * 16;
    if (ebase >= Eo) return;

    int i0[4], i1[4];
    #pragma unroll
    for (int j = 0; j < 4; j++) {
        long long e = ebase + j * 4 + g;
        int a = (e < Eo) ? ei[e] : 0;
        int b = (e < Eo) ? ei[e + Eo] : 0;
        i0[j] = min(max(a, 0), N - 1);
        i1[j] = min(max(b, 0), N - 1);
    }

    uint4 av[4], bv[4];
    #pragma unroll
    for (int j = 0; j < 4; j++) {
        av[j] = ((const uint4*)(g_reps_h + (size_t)i0[j] * 32))[sub];
        bv[j] = ((const uint4*)(g_reps_h + (size_t)i1[j] * 32))[sub];
    }

    float acc[4];
    #pragma unroll
    for (int j = 0; j < 4; j++) {
        acc[j] = dot8h(av[j], bv[j]);
        acc[j] += __shfl_xor_sync(0xffffffffu, acc[j], 4);
        acc[j] += __shfl_xor_sync(0xffffffffu, acc[j], 2);
        acc[j] += __shfl_xor_sync(0xffffffffu, acc[j], 1);
    }

    if (sub == 0) {
        #pragma unroll
        for (int j = 0; j < 4; j++) {
            long long e = ebase + j * 4 + g;
            if (e < Eo) pw[e] = fmaxf(acc[j], 0.f);
        }
    }
}

extern "C" void kernel_launch(void* const* d_in, const int* in_sizes, int n_in,
                              void* d_out, int out_size)
{
    const float* feat = (const float*)d_in[0];
    const int*   ei   = (const int*)d_in[1];
    const int*   pei  = (const int*)d_in[2];
    const float* W1   = (const float*)d_in[3];
    const float* b1   = (const float*)d_in[4];
    const float* W2   = (const float*)d_in[5];
    const float* b2   = (const float*)d_in[6];
    float* out = (float*)d_out;

    const int N        = in_sizes[0] / 128;
    const long long Eo = in_sizes[1] / 2;
    const long long Ec = in_sizes[2] / 2;

    float* reps    = out;
    float* pw      = out + (size_t)N * 64;
    float* out_tei = pw + Eo;
    float* out_ei  = out_tei + 2 * (Eo + Ec);

    cudaFuncSetAttribute(mlp_mma_kernel,
                         cudaFuncAttributeMaxDynamicSharedMemorySize, SMEM_BYTES);

    int mlp_blocks = (N + NODES_PER_BLK - 1) / NODES_PER_BLK;
    long long copy_items = (Eo > Ec ? Eo : Ec);
    int copy_blocks = (int)((copy_items + MLP_THREADS * 4 - 1) / (MLP_THREADS * 4));

    mlp_mma_kernel<<<mlp_blocks + copy_blocks, MLP_THREADS, SMEM_BYTES>>>(
        feat, W1, b1, W2, b2, reps, N, mlp_blocks,
        ei, pei, Eo, Ec, out_tei, out_ei);

    // warps of 16 edges each
    long long warps = (Eo + 15) / 16;
    long long threads = warps * 32;
    int edge_blocks = (int)((threads + 255) / 256);
    edge_dot_kernel<<<edge_blocks, 256>>>(ei, Eo, pw, N);
}

// round 12
// speedup vs baseline: 1.4525x; 1.0329x over previous
#include <cuda_runtime.h>
#include <cuda_fp16.h>
#include <cuda_bf16.h>
#include <cstdint>

// ---------------------------------------------------------------------------
// EstimateAdj:
//   h    = relu(features @ W1 + b1)   [N,128]->[N,64]
//   reps = h @ W2 + b2                [N,64]
//   pw[e] = relu(dot(reps[ei0[e]], reps[ei1[e]]))  e < Eo
// Output (float32 concat): reps | pw | total_edge_index | edge_index
//
// R12 vs R11 (76.3us):
//  - MLP precision scheme: bf16 3-pass -> fp16 2-pass.
//    Weights: 2-term fp16 split (hi+lo, ~2^-22 exact). Activations: single
//    fp16 (rel ~1.4e-4/GEMM). D = Ah*Bh + Ah*Bl. HMMA/warp 288->192, all
//    activation residual-split math removed.
//  - edge kernel unchanged (at LTS cap, 31.1us).
// Expected rel_err ~3e-4 (was 1.13e-4), threshold 1e-3.
// ---------------------------------------------------------------------------

#define MLP_THREADS 256
#define NODES_PER_BLK 128
#define N_MAX 100000

typedef unsigned int u32;

// fp16 shadow of reps (32 half2 per node = 128B/row) for the edge gather
__device__ __half2 g_reps_h[N_MAX * 32];

// smem layout (bytes):
//  Wt1h [64][136] f16 : 0      .. 17408   } GEMM phase
//  Wt1l [64][136] f16 : 17408  .. 34816   }
//  Wt2h [64][72]  f16 : 34816  .. 44032   }
//  Wt2l [64][72]  f16 : 44032  .. 53248   }
//  rstage [128][68] f32   : 0     .. 34816  } epilogue phase (reuses Wt1)
//  hstage [128][36] half2 : 34816 .. 53248  } epilogue phase (reuses Wt2)
//  b1s  [64] f32       : 53248  .. 53504   (never overwritten)
//  b2s  [64] f32       : 53504  .. 53760
#define SMEM_BYTES 53760
#define W1_STRIDE 136   // elements; 68 words/row -> (68*(8n+g)+t)%32 = (4g+t)%32
#define W2_STRIDE 72    // elements; 36 words/row -> same property
#define RSTAGE_STRIDE 68   // floats; 68%32=4 -> conflict-free
#define HSTAGE_STRIDE 36   // half2 words; 36%32=4 -> same

__device__ __forceinline__ void mma_f16(float* c, const u32* a, u32 b0, u32 b1) {
    asm volatile(
        "mma.sync.aligned.m16n8k16.row.col.f32.f16.f16.f32 "
        "{%0,%1,%2,%3}, {%4,%5,%6,%7}, {%8,%9}, {%0,%1,%2,%3};"
        : "+f"(c[0]), "+f"(c[1]), "+f"(c[2]), "+f"(c[3])
        : "r"(a[0]), "r"(a[1]), "r"(a[2]), "r"(a[3]), "r"(b0), "r"(b1));
}

__device__ __forceinline__ u32 pack2h(float x, float y) {
    __half2 h = __floats2half2_rn(x, y);
    return *(u32*)&h;
}

// MMA MLP + (role-split) index copy.
__global__ void __launch_bounds__(MLP_THREADS)
mlp_mma_kernel(const float* __restrict__ feat,
               const float* __restrict__ W1, const float* __restrict__ b1,
               const float* __restrict__ W2, const float* __restrict__ b2,
               float* __restrict__ reps, int N, int mlp_blocks,
               const int* __restrict__ ei, const int* __restrict__ pei,
               long long Eo, long long Ec,
               float* __restrict__ out_tei, float* __restrict__ out_ei)
{
    const int tx = threadIdx.x;

    if (blockIdx.x >= mlp_blocks) {
        // ---------------- index copy role (vectorized x4) ----------------
        long long i = ((long long)(blockIdx.x - mlp_blocks) * MLP_THREADS + tx) * 4;
        long long Et = Eo + Ec;
        if (i < Eo) {
            int4 v0 = *(const int4*)(ei + i);
            int4 v1 = *(const int4*)(ei + Eo + i);
            float4 f0 = make_float4((float)v0.x, (float)v0.y, (float)v0.z, (float)v0.w);
            float4 f1 = make_float4((float)v1.x, (float)v1.y, (float)v1.z, (float)v1.w);
            *(float4*)(out_tei + i)      = f0;
            *(float4*)(out_tei + Et + i) = f1;
            *(float4*)(out_ei + i)       = f0;
            *(float4*)(out_ei + Eo + i)  = f1;
        }
        if (i < Ec) {
            int4 v0 = *(const int4*)(pei + i);
            int4 v1 = *(const int4*)(pei + Ec + i);
            float4 f0 = make_float4((float)v0.x, (float)v0.y, (float)v0.z, (float)v0.w);
            float4 f1 = make_float4((float)v1.x, (float)v1.y, (float)v1.z, (float)v1.w);
            *(float4*)(out_tei + Eo + i)      = f0;
            *(float4*)(out_tei + Et + Eo + i) = f1;
        }
        return;
    }

    // ---------------- MLP role ----------------
    extern __shared__ char smc[];
    __half* Wt1h = (__half*)(smc);
    __half* Wt1l = (__half*)(smc + 17408);
    __half* Wt2h = (__half*)(smc + 34816);
    __half* Wt2l = (__half*)(smc + 44032);
    float* b1s = (float*)(smc + 53248);
    float* b2s = (float*)(smc + 53504);

    // Prologue: split W1, W2 to transposed fp16 hi/lo planes (hi+lo ~ exact).
    for (int idx = tx; idx < 128 * 64; idx += MLP_THREADS) {
        int k = idx >> 6, n = idx & 63;
        float w = W1[idx];
        __half hi = __float2half_rn(w);
        Wt1h[n * W1_STRIDE + k] = hi;
        Wt1l[n * W1_STRIDE + k] = __float2half_rn(w - __half2float(hi));
    }
    for (int idx = tx; idx < 64 * 64; idx += MLP_THREADS) {
        int k = idx >> 6, n = idx & 63;
        float w = W2[idx];
        __half hi = __float2half_rn(w);
        Wt2h[n * W2_STRIDE + k] = hi;
        Wt2l[n * W2_STRIDE + k] = __float2half_rn(w - __half2float(hi));
    }
    if (tx < 64) { b1s[tx] = b1[tx]; b2s[tx] = b2[tx]; }
    __syncthreads();

    const int warp = tx >> 5, lane = tx & 31;
    const int g = lane >> 2, t = lane & 3;
    const int r0 = blockIdx.x * NODES_PER_BLK + warp * 16 + g;
    const int r1 = r0 + 8;
    const bool v0 = r0 < N, v1 = r1 < N;
    const float* f0p = feat + (size_t)(v0 ? r0 : 0) * 128 + t * 2;
    const float* f1p = feat + (size_t)(v1 ? r1 : 0) * 128 + t * 2;

    // ---- GEMM1: C[8 n-tiles][4] over K=128 (8 k-steps), 2-pass fp16 ----
    float C[8][4];
    #pragma unroll
    for (int n = 0; n < 8; n++)
        #pragma unroll
        for (int i = 0; i < 4; i++) C[n][i] = 0.f;

    #pragma unroll 2
    for (int kt = 0; kt < 8; kt++) {
        float2 x00 = v0 ? *(const float2*)(f0p + kt * 16)     : make_float2(0.f, 0.f);
        float2 x01 = v0 ? *(const float2*)(f0p + kt * 16 + 8) : make_float2(0.f, 0.f);
        float2 x10 = v1 ? *(const float2*)(f1p + kt * 16)     : make_float2(0.f, 0.f);
        float2 x11 = v1 ? *(const float2*)(f1p + kt * 16 + 8) : make_float2(0.f, 0.f);
        u32 ah[4];
        ah[0] = pack2h(x00.x, x00.y);
        ah[1] = pack2h(x10.x, x10.y);
        ah[2] = pack2h(x01.x, x01.y);
        ah[3] = pack2h(x11.x, x11.y);

        const int kb = kt * 16 + t * 2;
        #pragma unroll
        for (int n = 0; n < 8; n++) {
            const __half* wh = Wt1h + (n * 8 + g) * W1_STRIDE + kb;
            const __half* wl = Wt1l + (n * 8 + g) * W1_STRIDE + kb;
            u32 bh0 = *(const u32*)(wh);
            u32 bh1 = *(const u32*)(wh + 8);
            u32 bl0 = *(const u32*)(wl);
            u32 bl1 = *(const u32*)(wl + 8);
            mma_f16(C[n], ah, bh0, bh1);
            mma_f16(C[n], ah, bl0, bl1);
        }
    }

    // bias + relu -> h (registers), then pack into GEMM2 A-frags (fp16).
    #pragma unroll
    for (int n = 0; n < 8; n++) {
        float bb0 = b1s[n * 8 + t * 2];
        float bb1 = b1s[n * 8 + t * 2 + 1];
        C[n][0] = fmaxf(C[n][0] + bb0, 0.f);
        C[n][1] = fmaxf(C[n][1] + bb1, 0.f);
        C[n][2] = fmaxf(C[n][2] + bb0, 0.f);
        C[n][3] = fmaxf(C[n][3] + bb1, 0.f);
    }

    u32 a2[4][4];
    #pragma unroll
    for (int kt = 0; kt < 4; kt++) {
        a2[kt][0] = pack2h(C[2 * kt][0],     C[2 * kt][1]);
        a2[kt][1] = pack2h(C[2 * kt][2],     C[2 * kt][3]);
        a2[kt][2] = pack2h(C[2 * kt + 1][0], C[2 * kt + 1][1]);
        a2[kt][3] = pack2h(C[2 * kt + 1][2], C[2 * kt + 1][3]);
    }

    // ---- GEMM2: D[8][4] over K=64 (4 k-steps), 2-pass fp16 ----
    float D[8][4];
    #pragma unroll
    for (int n = 0; n < 8; n++)
        #pragma unroll
        for (int i = 0; i < 4; i++) D[n][i] = 0.f;

    #pragma unroll
    for (int kt = 0; kt < 4; kt++) {
        const int kb = kt * 16 + t * 2;
        #pragma unroll
        for (int n = 0; n < 8; n++) {
            const __half* wh = Wt2h + (n * 8 + g) * W2_STRIDE + kb;
            const __half* wl = Wt2l + (n * 8 + g) * W2_STRIDE + kb;
            u32 bh0 = *(const u32*)(wh);
            u32 bh1 = *(const u32*)(wh + 8);
            u32 bl0 = *(const u32*)(wl);
            u32 bl1 = *(const u32*)(wl + 8);
            mma_f16(D[n], a2[kt], bh0, bh1);
            mma_f16(D[n], a2[kt], bl0, bl1);
        }
    }

    // ---- Epilogue: stage in smem (weight regions now dead), then coalesce ----
    __syncthreads();   // all warps done reading Wt1/Wt2
    float*   rstage = (float*)smc;                 // [128][68]
    __half2* hstage = (__half2*)(smc + 34816);     // [128][36]

    const int lr0 = warp * 16 + g;
    const int lr1 = lr0 + 8;
    #pragma unroll
    for (int n = 0; n < 8; n++) {
        int c0 = n * 8 + t * 2;
        float bb0 = b2s[c0], bb1 = b2s[c0 + 1];
        float2 o0 = make_float2(D[n][0] + bb0, D[n][1] + bb1);
        float2 o1 = make_float2(D[n][2] + bb0, D[n][3] + bb1);
        rstage[lr0 * RSTAGE_STRIDE + c0]     = o0.x;
        rstage[lr0 * RSTAGE_STRIDE + c0 + 1] = o0.y;
        rstage[lr1 * RSTAGE_STRIDE + c0]     = o1.x;
        rstage[lr1 * RSTAGE_STRIDE + c0 + 1] = o1.y;
        hstage[lr0 * HSTAGE_STRIDE + (c0 >> 1)] = __floats2half2_rn(o0.x, o0.y);
        hstage[lr1 * HSTAGE_STRIDE + (c0 >> 1)] = __floats2half2_rn(o1.x, o1.y);
    }
    __syncthreads();

    const int base_row = blockIdx.x * NODES_PER_BLK;
    // reps: 128 rows x 16 float4, coalesced
    for (int i = tx; i < 128 * 16; i += MLP_THREADS) {
        int row = i >> 4, c = i & 15;
        int grow = base_row + row;
        if (grow < N) {
            const float* s = rstage + row * RSTAGE_STRIDE + c * 4;
            float4 v = make_float4(s[0], s[1], s[2], s[3]);
            *(float4*)(reps + (size_t)grow * 64 + c * 4) = v;
        }
    }
    // shadow: 128 rows x 8 uint4, coalesced
    for (int i = tx; i < 128 * 8; i += MLP_THREADS) {
        int row = i >> 3, c = i & 7;
        int grow = base_row + row;
        if (grow < N) {
            uint4 v = *(const uint4*)(hstage + row * HSTAGE_STRIDE + c * 4);
            *(uint4*)(g_reps_h + (size_t)grow * 32 + c * 4) = v;
        }
    }
}

__device__ __forceinline__ float dot8h(uint4 a, uint4 b) {
    const __half2* pa = (const __half2*)&a;
    const __half2* pb = (const __half2*)&b;
    float acc = 0.f;
    #pragma unroll
    for (int j = 0; j < 4; j++) {
        float2 x = __half22float2(pa[j]);
        float2 y = __half22float2(pb[j]);
        acc = fmaf(x.x, y.x, acc);
        acc = fmaf(x.y, y.y, acc);
    }
    return acc;
}

// Edge dots (R9/R11 version verbatim): 8 lanes/edge, 4 edges/thread.
__global__ void __launch_bounds__(256)
edge_dot_kernel(const int* __restrict__ ei, long long Eo,
                float* __restrict__ pw, int N)
{
    const int lane = threadIdx.x & 31;
    const int sub = lane & 7;      // 16B chunk within the 128B row
    const int g = lane >> 3;       // edge slot within warp (0..3)
    long long warp_g = ((long long)blockIdx.x * blockDim.x + threadIdx.x) >> 5;
    long long ebase = warp_g * 16;
    if (ebase >= Eo) return;

    int i0[4], i1[4];
    #pragma unroll
    for (int j = 0; j < 4; j++) {
        long long e = ebase + j * 4 + g;
        int a = (e < Eo) ? ei[e] : 0;
        int b = (e < Eo) ? ei[e + Eo] : 0;
        i0[j] = min(max(a, 0), N - 1);
        i1[j] = min(max(b, 0), N - 1);
    }

    uint4 av[4], bv[4];
    #pragma unroll
    for (int j = 0; j < 4; j++) {
        av[j] = ((const uint4*)(g_reps_h + (size_t)i0[j] * 32))[sub];
        bv[j] = ((const uint4*)(g_reps_h + (size_t)i1[j] * 32))[sub];
    }

    float acc[4];
    #pragma unroll
    for (int j = 0; j < 4; j++) {
        acc[j] = dot8h(av[j], bv[j]);
        acc[j] += __shfl_xor_sync(0xffffffffu, acc[j], 4);
        acc[j] += __shfl_xor_sync(0xffffffffu, acc[j], 2);
        acc[j] += __shfl_xor_sync(0xffffffffu, acc[j], 1);
    }

    if (sub == 0) {
        #pragma unroll
        for (int j = 0; j < 4; j++) {
            long long e = ebase + j * 4 + g;
            if (e < Eo) pw[e] = fmaxf(acc[j], 0.f);
        }
    }
}

extern "C" void kernel_launch(void* const* d_in, const int* in_sizes, int n_in,
                              void* d_out, int out_size)
{
    const float* feat = (const float*)d_in[0];
    const int*   ei   = (const int*)d_in[1];
    const int*   pei  = (const int*)d_in[2];
    const float* W1   = (const float*)d_in[3];
    const float* b1   = (const float*)d_in[4];
    const float* W2   = (const float*)d_in[5];
    const float* b2   = (const float*)d_in[6];
    float* out = (float*)d_out;

    const int N        = in_sizes[0] / 128;
    const long long Eo = in_sizes[1] / 2;
    const long long Ec = in_sizes[2] / 2;

    float* reps    = out;
    float* pw      = out + (size_t)N * 64;
    float* out_tei = pw + Eo;
    float* out_ei  = out_tei + 2 * (Eo + Ec);

    cudaFuncSetAttribute(mlp_mma_kernel,
                         cudaFuncAttributeMaxDynamicSharedMemorySize, SMEM_BYTES);

    int mlp_blocks = (N + NODES_PER_BLK - 1) / NODES_PER_BLK;
    long long copy_items = (Eo > Ec ? Eo : Ec);
    int copy_blocks = (int)((copy_items + MLP_THREADS * 4 - 1) / (MLP_THREADS * 4));

    mlp_mma_kernel<<<mlp_blocks + copy_blocks, MLP_THREADS, SMEM_BYTES>>>(
        feat, W1, b1, W2, b2, reps, N, mlp_blocks,
        ei, pei, Eo, Ec, out_tei, out_ei);

    // warps of 16 edges each
    long long warps = (Eo + 15) / 16;
    long long threads = warps * 32;
    int edge_blocks = (int)((threads + 255) / 256);
    edge_dot_kernel<<<edge_blocks, 256>>>(ei, Eo, pw, N);
}

// round 13
// speedup vs baseline: 1.4867x; 1.0235x over previous
#include <cuda_runtime.h>
#include <cuda_fp16.h>
#include <cuda_bf16.h>
#include <cstdint>

// ---------------------------------------------------------------------------
// EstimateAdj:
//   h    = relu(features @ W1 + b1)   [N,128]->[N,64]
//   reps = h @ W2 + b2                [N,64]
//   pw[e] = relu(dot(reps[ei0[e]], reps[ei1[e]]))  e < Eo
// Output (float32 concat): reps | pw | total_edge_index | edge_index
//
// R13 vs R12 (73.8us): occupancy attack on the latency-bound MLP launch.
//  - __launch_bounds__(256, 3): 2 -> 3 CTAs/SM (+50% warps)
//  - GEMM2 single-fp16 weights (drop W2-lo pass): smaller live set + smem
//  - fp16 shadow derived from rstage in the writer (hstage removed);
//    smem 53.8KB -> 44.5KB so 3 CTAs fit
//  - edge kernel unchanged (at LTS cap, 30.9us)
// Expected rel_err ~3.3e-4 (threshold 1e-3).
// ---------------------------------------------------------------------------

#define MLP_THREADS 256
#define NODES_PER_BLK 128
#define N_MAX 100000

typedef unsigned int u32;

// fp16 shadow of reps (32 half2 per node = 128B/row) for the edge gather
__device__ __half2 g_reps_h[N_MAX * 32];

// smem layout (bytes):
//  Wt1h [64][136] f16 : 0      .. 17408   } GEMM phase
//  Wt1l [64][136] f16 : 17408  .. 34816   }
//  Wt2h [64][72]  f16 : 34816  .. 44032   }
//  b1s  [64] f32      : 44032  .. 44288   (never overwritten)
//  b2s  [64] f32      : 44288  .. 44544
//  rstage [128][68] f32 : 0 .. 34816      } epilogue phase (reuses Wt1)
#define SMEM_BYTES 44544
#define W1_STRIDE 136   // elements; 68 words/row -> (68*(8n+g)+t)%32 = (4g+t)%32
#define W2_STRIDE 72    // elements; 36 words/row -> same property
#define RSTAGE_STRIDE 68   // floats; 68%32=4 -> conflict-free stage writes

__device__ __forceinline__ void mma_f16(float* c, const u32* a, u32 b0, u32 b1) {
    asm volatile(
        "mma.sync.aligned.m16n8k16.row.col.f32.f16.f16.f32 "
        "{%0,%1,%2,%3}, {%4,%5,%6,%7}, {%8,%9}, {%0,%1,%2,%3};"
        : "+f"(c[0]), "+f"(c[1]), "+f"(c[2]), "+f"(c[3])
        : "r"(a[0]), "r"(a[1]), "r"(a[2]), "r"(a[3]), "r"(b0), "r"(b1));
}

__device__ __forceinline__ u32 pack2h(float x, float y) {
    __half2 h = __floats2half2_rn(x, y);
    return *(u32*)&h;
}

// MMA MLP + (role-split) index copy.
__global__ void __launch_bounds__(MLP_THREADS, 3)
mlp_mma_kernel(const float* __restrict__ feat,
               const float* __restrict__ W1, const float* __restrict__ b1,
               const float* __restrict__ W2, const float* __restrict__ b2,
               float* __restrict__ reps, int N, int mlp_blocks,
               const int* __restrict__ ei, const int* __restrict__ pei,
               long long Eo, long long Ec,
               float* __restrict__ out_tei, float* __restrict__ out_ei)
{
    const int tx = threadIdx.x;

    if (blockIdx.x >= mlp_blocks) {
        // ---------------- index copy role (vectorized x4) ----------------
        long long i = ((long long)(blockIdx.x - mlp_blocks) * MLP_THREADS + tx) * 4;
        long long Et = Eo + Ec;
        if (i < Eo) {
            int4 v0 = *(const int4*)(ei + i);
            int4 v1 = *(const int4*)(ei + Eo + i);
            float4 f0 = make_float4((float)v0.x, (float)v0.y, (float)v0.z, (float)v0.w);
            float4 f1 = make_float4((float)v1.x, (float)v1.y, (float)v1.z, (float)v1.w);
            *(float4*)(out_tei + i)      = f0;
            *(float4*)(out_tei + Et + i) = f1;
            *(float4*)(out_ei + i)       = f0;
            *(float4*)(out_ei + Eo + i)  = f1;
        }
        if (i < Ec) {
            int4 v0 = *(const int4*)(pei + i);
            int4 v1 = *(const int4*)(pei + Ec + i);
            float4 f0 = make_float4((float)v0.x, (float)v0.y, (float)v0.z, (float)v0.w);
            float4 f1 = make_float4((float)v1.x, (float)v1.y, (float)v1.z, (float)v1.w);
            *(float4*)(out_tei + Eo + i)      = f0;
            *(float4*)(out_tei + Et + Eo + i) = f1;
        }
        return;
    }

    // ---------------- MLP role ----------------
    extern __shared__ char smc[];
    __half* Wt1h = (__half*)(smc);
    __half* Wt1l = (__half*)(smc + 17408);
    __half* Wt2h = (__half*)(smc + 34816);
    float* b1s = (float*)(smc + 44032);
    float* b2s = (float*)(smc + 44288);

    // Prologue: W1 split to fp16 hi/lo planes (hi+lo ~exact); W2 single fp16.
    for (int idx = tx; idx < 128 * 64; idx += MLP_THREADS) {
        int k = idx >> 6, n = idx & 63;
        float w = W1[idx];
        __half hi = __float2half_rn(w);
        Wt1h[n * W1_STRIDE + k] = hi;
        Wt1l[n * W1_STRIDE + k] = __float2half_rn(w - __half2float(hi));
    }
    for (int idx = tx; idx < 64 * 64; idx += MLP_THREADS) {
        int k = idx >> 6, n = idx & 63;
        Wt2h[n * W2_STRIDE + k] = __float2half_rn(W2[idx]);
    }
    if (tx < 64) { b1s[tx] = b1[tx]; b2s[tx] = b2[tx]; }
    __syncthreads();

    const int warp = tx >> 5, lane = tx & 31;
    const int g = lane >> 2, t = lane & 3;
    const int r0 = blockIdx.x * NODES_PER_BLK + warp * 16 + g;
    const int r1 = r0 + 8;
    const bool v0 = r0 < N, v1 = r1 < N;
    const float* f0p = feat + (size_t)(v0 ? r0 : 0) * 128 + t * 2;
    const float* f1p = feat + (size_t)(v1 ? r1 : 0) * 128 + t * 2;

    // ---- GEMM1: C[8 n-tiles][4] over K=128 (8 k-steps), 2-pass fp16 ----
    float C[8][4];
    #pragma unroll
    for (int n = 0; n < 8; n++)
        #pragma unroll
        for (int i = 0; i < 4; i++) C[n][i] = 0.f;

    #pragma unroll 2
    for (int kt = 0; kt < 8; kt++) {
        float2 x00 = v0 ? *(const float2*)(f0p + kt * 16)     : make_float2(0.f, 0.f);
        float2 x01 = v0 ? *(const float2*)(f0p + kt * 16 + 8) : make_float2(0.f, 0.f);
        float2 x10 = v1 ? *(const float2*)(f1p + kt * 16)     : make_float2(0.f, 0.f);
        float2 x11 = v1 ? *(const float2*)(f1p + kt * 16 + 8) : make_float2(0.f, 0.f);
        u32 ah[4];
        ah[0] = pack2h(x00.x, x00.y);
        ah[1] = pack2h(x10.x, x10.y);
        ah[2] = pack2h(x01.x, x01.y);
        ah[3] = pack2h(x11.x, x11.y);

        const int kb = kt * 16 + t * 2;
        #pragma unroll
        for (int n = 0; n < 8; n++) {
            const __half* wh = Wt1h + (n * 8 + g) * W1_STRIDE + kb;
            const __half* wl = Wt1l + (n * 8 + g) * W1_STRIDE + kb;
            u32 bh0 = *(const u32*)(wh);
            u32 bh1 = *(const u32*)(wh + 8);
            u32 bl0 = *(const u32*)(wl);
            u32 bl1 = *(const u32*)(wl + 8);
            mma_f16(C[n], ah, bh0, bh1);
            mma_f16(C[n], ah, bl0, bl1);
        }
    }

    // bias + relu -> h (registers), then pack into GEMM2 A-frags (fp16).
    #pragma unroll
    for (int n = 0; n < 8; n++) {
        float bb0 = b1s[n * 8 + t * 2];
        float bb1 = b1s[n * 8 + t * 2 + 1];
        C[n][0] = fmaxf(C[n][0] + bb0, 0.f);
        C[n][1] = fmaxf(C[n][1] + bb1, 0.f);
        C[n][2] = fmaxf(C[n][2] + bb0, 0.f);
        C[n][3] = fmaxf(C[n][3] + bb1, 0.f);
    }

    u32 a2[4][4];
    #pragma unroll
    for (int kt = 0; kt < 4; kt++) {
        a2[kt][0] = pack2h(C[2 * kt][0],     C[2 * kt][1]);
        a2[kt][1] = pack2h(C[2 * kt][2],     C[2 * kt][3]);
        a2[kt][2] = pack2h(C[2 * kt + 1][0], C[2 * kt + 1][1]);
        a2[kt][3] = pack2h(C[2 * kt + 1][2], C[2 * kt + 1][3]);
    }

    // ---- GEMM2: D[8][4] over K=64 (4 k-steps), single-pass fp16 ----
    float D[8][4];
    #pragma unroll
    for (int n = 0; n < 8; n++)
        #pragma unroll
        for (int i = 0; i < 4; i++) D[n][i] = 0.f;

    #pragma unroll
    for (int kt = 0; kt < 4; kt++) {
        const int kb = kt * 16 + t * 2;
        #pragma unroll
        for (int n = 0; n < 8; n++) {
            const __half* wh = Wt2h + (n * 8 + g) * W2_STRIDE + kb;
            u32 bh0 = *(const u32*)(wh);
            u32 bh1 = *(const u32*)(wh + 8);
            mma_f16(D[n], a2[kt], bh0, bh1);
        }
    }

    // ---- Epilogue: stage fp32 in smem (Wt1 region dead), coalesced write ----
    __syncthreads();   // all warps done reading Wt1/Wt2
    float* rstage = (float*)smc;                 // [128][68]

    const int lr0 = warp * 16 + g;
    const int lr1 = lr0 + 8;
    #pragma unroll
    for (int n = 0; n < 8; n++) {
        int c0 = n * 8 + t * 2;
        float bb0 = b2s[c0], bb1 = b2s[c0 + 1];
        rstage[lr0 * RSTAGE_STRIDE + c0]     = D[n][0] + bb0;
        rstage[lr0 * RSTAGE_STRIDE + c0 + 1] = D[n][1] + bb1;
        rstage[lr1 * RSTAGE_STRIDE + c0]     = D[n][2] + bb0;
        rstage[lr1 * RSTAGE_STRIDE + c0 + 1] = D[n][3] + bb1;
    }
    __syncthreads();

    const int base_row = blockIdx.x * NODES_PER_BLK;
    // reps: 128 rows x 16 float4, coalesced
    for (int i = tx; i < 128 * 16; i += MLP_THREADS) {
        int row = i >> 4, c = i & 15;
        int grow = base_row + row;
        if (grow < N) {
            const float* s = rstage + row * RSTAGE_STRIDE + c * 4;
            float4 v = make_float4(s[0], s[1], s[2], s[3]);
            *(float4*)(reps + (size_t)grow * 64 + c * 4) = v;
        }
    }
    // shadow: 128 rows x 8 uint4, converted from rstage, coalesced
    for (int i = tx; i < 128 * 8; i += MLP_THREADS) {
        int row = i >> 3, c = i & 7;
        int grow = base_row + row;
        if (grow < N) {
            const float* s = rstage + row * RSTAGE_STRIDE + c * 8;
            uint4 v;
            v.x = pack2h(s[0], s[1]);
            v.y = pack2h(s[2], s[3]);
            v.z = pack2h(s[4], s[5]);
            v.w = pack2h(s[6], s[7]);
            *(uint4*)(g_reps_h + (size_t)grow * 32 + c * 4) = v;
        }
    }
}

__device__ __forceinline__ float dot8h(uint4 a, uint4 b) {
    const __half2* pa = (const __half2*)&a;
    const __half2* pb = (const __half2*)&b;
    float acc = 0.f;
    #pragma unroll
    for (int j = 0; j < 4; j++) {
        float2 x = __half22float2(pa[j]);
        float2 y = __half22float2(pb[j]);
        acc = fmaf(x.x, y.x, acc);
        acc = fmaf(x.y, y.y, acc);
    }
    return acc;
}

// Edge dots (R9/R11 version verbatim): 8 lanes/edge, 4 edges/thread.
__global__ void __launch_bounds__(256)
edge_dot_kernel(const int* __restrict__ ei, long long Eo,
                float* __restrict__ pw, int N)
{
    const int lane = threadIdx.x & 31;
    const int sub = lane & 7;      // 16B chunk within the 128B row
    const int g = lane >> 3;       // edge slot within warp (0..3)
    long long warp_g = ((long long)blockIdx.x * blockDim.x + threadIdx.x) >> 5;
    long long ebase = warp_g * 16;
    if (ebase >= Eo) return;

    int i0[4], i1[4];
    #pragma unroll
    for (int j = 0; j < 4; j++) {
        long long e = ebase + j * 4 + g;
        int a = (e < Eo) ? ei[e] : 0;
        int b = (e < Eo) ? ei[e + Eo] : 0;
        i0[j] = min(max(a, 0), N - 1);
        i1[j] = min(max(b, 0), N - 1);
    }

    uint4 av[4], bv[4];
    #pragma unroll
    for (int j = 0; j < 4; j++) {
        av[j] = ((const uint4*)(g_reps_h + (size_t)i0[j] * 32))[sub];
        bv[j] = ((const uint4*)(g_reps_h + (size_t)i1[j] * 32))[sub];
    }

    float acc[4];
    #pragma unroll
    for (int j = 0; j < 4; j++) {
        acc[j] = dot8h(av[j], bv[j]);
        acc[j] += __shfl_xor_sync(0xffffffffu, acc[j], 4);
        acc[j] += __shfl_xor_sync(0xffffffffu, acc[j], 2);
        acc[j] += __shfl_xor_sync(0xffffffffu, acc[j], 1);
    }

    if (sub == 0) {
        #pragma unroll
        for (int j = 0; j < 4; j++) {
            long long e = ebase + j * 4 + g;
            if (e < Eo) pw[e] = fmaxf(acc[j], 0.f);
        }
    }
}

extern "C" void kernel_launch(void* const* d_in, const int* in_sizes, int n_in,
                              void* d_out, int out_size)
{
    const float* feat = (const float*)d_in[0];
    const int*   ei   = (const int*)d_in[1];
    const int*   pei  = (const int*)d_in[2];
    const float* W1   = (const float*)d_in[3];
    const float* b1   = (const float*)d_in[4];
    const float* W2   = (const float*)d_in[5];
    const float* b2   = (const float*)d_in[6];
    float* out = (float*)d_out;

    const int N        = in_sizes[0] / 128;
    const long long Eo = in_sizes[1] / 2;
    const long long Ec = in_sizes[2] / 2;

    float* reps    = out;
    float* pw      = out + (size_t)N * 64;
    float* out_tei = pw + Eo;
    float* out_ei  = out_tei + 2 * (Eo + Ec);

    cudaFuncSetAttribute(mlp_mma_kernel,
                         cudaFuncAttributeMaxDynamicSharedMemorySize, SMEM_BYTES);

    int mlp_blocks = (N + NODES_PER_BLK - 1) / NODES_PER_BLK;
    long long copy_items = (Eo > Ec ? Eo : Ec);
    int copy_blocks = (int)((copy_items + MLP_THREADS * 4 - 1) / (MLP_THREADS * 4));

    mlp_mma_kernel<<<mlp_blocks + copy_blocks, MLP_THREADS, SMEM_BYTES>>>(
        feat, W1, b1, W2, b2, reps, N, mlp_blocks,
        ei, pei, Eo, Ec, out_tei, out_ei);

    // warps of 16 edges each
    long long warps = (Eo + 15) / 16;
    long long threads = warps * 32;
    int edge_blocks = (int)((threads + 255) / 256);
    edge_dot_kernel<<<edge_blocks, 256>>>(ei, Eo, pw, N);
}

// round 14
// speedup vs baseline: 1.6697x; 1.1231x over previous
#include <cuda_runtime.h>
#include <cuda_fp16.h>
#include <cuda_bf16.h>
#include <cstdint>

// ---------------------------------------------------------------------------
// EstimateAdj:
//   h    = relu(features @ W1 + b1)   [N,128]->[N,64]
//   reps = h @ W2 + b2                [N,64]
//   pw[e] = relu(dot(reps[ei0[e]], reps[ei1[e]]))  e < Eo
// Output (float32 concat): reps | pw | total_edge_index | edge_index
//
// R14 vs R13 (72.1us): hoist the per-block weight fp16-split (was redone by
// all 782 MLP blocks, ~200 instrs/thread) into a one-shot prep kernel that
// writes a gmem blob laid out exactly like the smem image; MLP prologue is
// now an 11x uint4 memcpy per thread. Numerics identical.
//  - edge kernel unchanged (at LTS cap)
// ---------------------------------------------------------------------------

#define MLP_THREADS 256
#define NODES_PER_BLK 128
#define N_MAX 100000

typedef unsigned int u32;

// fp16 shadow of reps (32 half2 per node = 128B/row) for the edge gather
__device__ __half2 g_reps_h[N_MAX * 32];

// Pre-converted weight planes, laid out exactly like the smem image:
//  [0, 17408)      Wt1h [64][136] f16
//  [17408, 34816)  Wt1l [64][136] f16
//  [34816, 44032)  Wt2h [64][72]  f16
#define WPACK_BYTES 44032
__device__ __align__(16) unsigned char g_wpack[WPACK_BYTES];

// smem layout (bytes):
//  Wt1h/Wt1l/Wt2h: as g_wpack         } GEMM phase
//  b1s [64] f32 : 44032 .. 44288      (never overwritten)
//  b2s [64] f32 : 44288 .. 44544
//  rstage [128][68] f32 : 0 .. 34816  } epilogue phase (reuses Wt1)
#define SMEM_BYTES 44544
#define W1_STRIDE 136   // elements; 68 words/row -> (68*(8n+g)+t)%32 = (4g+t)%32
#define W2_STRIDE 72    // elements; 36 words/row -> same property
#define RSTAGE_STRIDE 68   // floats; 68%32=4 -> conflict-free stage writes

__device__ __forceinline__ void mma_f16(float* c, const u32* a, u32 b0, u32 b1) {
    asm volatile(
        "mma.sync.aligned.m16n8k16.row.col.f32.f16.f16.f32 "
        "{%0,%1,%2,%3}, {%4,%5,%6,%7}, {%8,%9}, {%0,%1,%2,%3};"
        : "+f"(c[0]), "+f"(c[1]), "+f"(c[2]), "+f"(c[3])
        : "r"(a[0]), "r"(a[1]), "r"(a[2]), "r"(a[3]), "r"(b0), "r"(b1));
}

__device__ __forceinline__ u32 pack2h(float x, float y) {
    __half2 h = __floats2half2_rn(x, y);
    return *(u32*)&h;
}

// One-shot: convert W1 (fp16 hi/lo split) and W2 (single fp16) into g_wpack.
// grid 48 x 256 = 12288 threads = one per weight element.
__global__ void __launch_bounds__(256)
weight_prep_kernel(const float* __restrict__ W1, const float* __restrict__ W2)
{
    int idx = blockIdx.x * 256 + threadIdx.x;
    __half* w1h = (__half*)(g_wpack);
    __half* w1l = (__half*)(g_wpack + 17408);
    __half* w2h = (__half*)(g_wpack + 34816);
    if (idx < 128 * 64) {
        int k = idx >> 6, n = idx & 63;
        float w = W1[idx];
        __half hi = __float2half_rn(w);
        w1h[n * W1_STRIDE + k] = hi;
        w1l[n * W1_STRIDE + k] = __float2half_rn(w - __half2float(hi));
    } else {
        int j = idx - 128 * 64;   // [0, 4096)
        int k = j >> 6, n = j & 63;
        w2h[n * W2_STRIDE + k] = __float2half_rn(W2[j]);
    }
}

// MMA MLP + (role-split) index copy.
__global__ void __launch_bounds__(MLP_THREADS, 3)
mlp_mma_kernel(const float* __restrict__ feat,
               const float* __restrict__ b1, const float* __restrict__ b2,
               float* __restrict__ reps, int N, int mlp_blocks,
               const int* __restrict__ ei, const int* __restrict__ pei,
               long long Eo, long long Ec,
               float* __restrict__ out_tei, float* __restrict__ out_ei)
{
    const int tx = threadIdx.x;

    if (blockIdx.x >= mlp_blocks) {
        // ---------------- index copy role (vectorized x4) ----------------
        long long i = ((long long)(blockIdx.x - mlp_blocks) * MLP_THREADS + tx) * 4;
        long long Et = Eo + Ec;
        if (i < Eo) {
            int4 v0 = *(const int4*)(ei + i);
            int4 v1 = *(const int4*)(ei + Eo + i);
            float4 f0 = make_float4((float)v0.x, (float)v0.y, (float)v0.z, (float)v0.w);
            float4 f1 = make_float4((float)v1.x, (float)v1.y, (float)v1.z, (float)v1.w);
            *(float4*)(out_tei + i)      = f0;
            *(float4*)(out_tei + Et + i) = f1;
            *(float4*)(out_ei + i)       = f0;
            *(float4*)(out_ei + Eo + i)  = f1;
        }
        if (i < Ec) {
            int4 v0 = *(const int4*)(pei + i);
            int4 v1 = *(const int4*)(pei + Ec + i);
            float4 f0 = make_float4((float)v0.x, (float)v0.y, (float)v0.z, (float)v0.w);
            float4 f1 = make_float4((float)v1.x, (float)v1.y, (float)v1.z, (float)v1.w);
            *(float4*)(out_tei + Eo + i)      = f0;
            *(float4*)(out_tei + Et + Eo + i) = f1;
        }
        return;
    }

    // ---------------- MLP role ----------------
    extern __shared__ char smc[];
    __half* Wt1h = (__half*)(smc);
    __half* Wt1l = (__half*)(smc + 17408);
    __half* Wt2h = (__half*)(smc + 34816);
    float* b1s = (float*)(smc + 44032);
    float* b2s = (float*)(smc + 44288);

    // Prologue: bulk-copy pre-converted weight planes (uint4, coalesced).
    {
        const uint4* src = (const uint4*)g_wpack;
        uint4* dst = (uint4*)smc;
        #pragma unroll
        for (int i = 0; i < WPACK_BYTES / 16 / MLP_THREADS + 1; i++) {
            int j = tx + i * MLP_THREADS;
            if (j < WPACK_BYTES / 16) dst[j] = src[j];
        }
    }
    if (tx < 64) { b1s[tx] = b1[tx]; b2s[tx] = b2[tx]; }
    __syncthreads();

    const int warp = tx >> 5, lane = tx & 31;
    const int g = lane >> 2, t = lane & 3;
    const int r0 = blockIdx.x * NODES_PER_BLK + warp * 16 + g;
    const int r1 = r0 + 8;
    const bool v0 = r0 < N, v1 = r1 < N;
    const float* f0p = feat + (size_t)(v0 ? r0 : 0) * 128 + t * 2;
    const float* f1p = feat + (size_t)(v1 ? r1 : 0) * 128 + t * 2;

    // ---- GEMM1: C[8 n-tiles][4] over K=128 (8 k-steps), 2-pass fp16 ----
    float C[8][4];
    #pragma unroll
    for (int n = 0; n < 8; n++)
        #pragma unroll
        for (int i = 0; i < 4; i++) C[n][i] = 0.f;

    #pragma unroll 2
    for (int kt = 0; kt < 8; kt++) {
        float2 x00 = v0 ? *(const float2*)(f0p + kt * 16)     : make_float2(0.f, 0.f);
        float2 x01 = v0 ? *(const float2*)(f0p + kt * 16 + 8) : make_float2(0.f, 0.f);
        float2 x10 = v1 ? *(const float2*)(f1p + kt * 16)     : make_float2(0.f, 0.f);
        float2 x11 = v1 ? *(const float2*)(f1p + kt * 16 + 8) : make_float2(0.f, 0.f);
        u32 ah[4];
        ah[0] = pack2h(x00.x, x00.y);
        ah[1] = pack2h(x10.x, x10.y);
        ah[2] = pack2h(x01.x, x01.y);
        ah[3] = pack2h(x11.x, x11.y);

        const int kb = kt * 16 + t * 2;
        #pragma unroll
        for (int n = 0; n < 8; n++) {
            const __half* wh = Wt1h + (n * 8 + g) * W1_STRIDE + kb;
            const __half* wl = Wt1l + (n * 8 + g) * W1_STRIDE + kb;
            u32 bh0 = *(const u32*)(wh);
            u32 bh1 = *(const u32*)(wh + 8);
            u32 bl0 = *(const u32*)(wl);
            u32 bl1 = *(const u32*)(wl + 8);
            mma_f16(C[n], ah, bh0, bh1);
            mma_f16(C[n], ah, bl0, bl1);
        }
    }

    // bias + relu -> h (registers), then pack into GEMM2 A-frags (fp16).
    #pragma unroll
    for (int n = 0; n < 8; n++) {
        float bb0 = b1s[n * 8 + t * 2];
        float bb1 = b1s[n * 8 + t * 2 + 1];
        C[n][0] = fmaxf(C[n][0] + bb0, 0.f);
        C[n][1] = fmaxf(C[n][1] + bb1, 0.f);
        C[n][2] = fmaxf(C[n][2] + bb0, 0.f);
        C[n][3] = fmaxf(C[n][3] + bb1, 0.f);
    }

    u32 a2[4][4];
    #pragma unroll
    for (int kt = 0; kt < 4; kt++) {
        a2[kt][0] = pack2h(C[2 * kt][0],     C[2 * kt][1]);
        a2[kt][1] = pack2h(C[2 * kt][2],     C[2 * kt][3]);
        a2[kt][2] = pack2h(C[2 * kt + 1][0], C[2 * kt + 1][1]);
        a2[kt][3] = pack2h(C[2 * kt + 1][2], C[2 * kt + 1][3]);
    }

    // ---- GEMM2: D[8][4] over K=64 (4 k-steps), single-pass fp16 ----
    float D[8][4];
    #pragma unroll
    for (int n = 0; n < 8; n++)
        #pragma unroll
        for (int i = 0; i < 4; i++) D[n][i] = 0.f;

    #pragma unroll
    for (int kt = 0; kt < 4; kt++) {
        const int kb = kt * 16 + t * 2;
        #pragma unroll
        for (int n = 0; n < 8; n++) {
            const __half* wh = Wt2h + (n * 8 + g) * W2_STRIDE + kb;
            u32 bh0 = *(const u32*)(wh);
            u32 bh1 = *(const u32*)(wh + 8);
            mma_f16(D[n], a2[kt], bh0, bh1);
        }
    }

    // ---- Epilogue: stage fp32 in smem (Wt1 region dead), coalesced write ----
    __syncthreads();   // all warps done reading Wt1/Wt2
    float* rstage = (float*)smc;                 // [128][68]

    const int lr0 = warp * 16 + g;
    const int lr1 = lr0 + 8;
    #pragma unroll
    for (int n = 0; n < 8; n++) {
        int c0 = n * 8 + t * 2;
        float bb0 = b2s[c0], bb1 = b2s[c0 + 1];
        rstage[lr0 * RSTAGE_STRIDE + c0]     = D[n][0] + bb0;
        rstage[lr0 * RSTAGE_STRIDE + c0 + 1] = D[n][1] + bb1;
        rstage[lr1 * RSTAGE_STRIDE + c0]     = D[n][2] + bb0;
        rstage[lr1 * RSTAGE_STRIDE + c0 + 1] = D[n][3] + bb1;
    }
    __syncthreads();

    const int base_row = blockIdx.x * NODES_PER_BLK;
    // reps: 128 rows x 16 float4, coalesced
    for (int i = tx; i < 128 * 16; i += MLP_THREADS) {
        int row = i >> 4, c = i & 15;
        int grow = base_row + row;
        if (grow < N) {
            const float* s = rstage + row * RSTAGE_STRIDE + c * 4;
            float4 v = make_float4(s[0], s[1], s[2], s[3]);
            *(float4*)(reps + (size_t)grow * 64 + c * 4) = v;
        }
    }
    // shadow: 128 rows x 8 uint4, converted from rstage, coalesced
    for (int i = tx; i < 128 * 8; i += MLP_THREADS) {
        int row = i >> 3, c = i & 7;
        int grow = base_row + row;
        if (grow < N) {
            const float* s = rstage + row * RSTAGE_STRIDE + c * 8;
            uint4 v;
            v.x = pack2h(s[0], s[1]);
            v.y = pack2h(s[2], s[3]);
            v.z = pack2h(s[4], s[5]);
            v.w = pack2h(s[6], s[7]);
            *(uint4*)(g_reps_h + (size_t)grow * 32 + c * 4) = v;
        }
    }
}

__device__ __forceinline__ float dot8h(uint4 a, uint4 b) {
    const __half2* pa = (const __half2*)&a;
    const __half2* pb = (const __half2*)&b;
    float acc = 0.f;
    #pragma unroll
    for (int j = 0; j < 4; j++) {
        float2 x = __half22float2(pa[j]);
        float2 y = __half22float2(pb[j]);
        acc = fmaf(x.x, y.x, acc);
        acc = fmaf(x.y, y.y, acc);
    }
    return acc;
}

// Edge dots (frozen since R9): 8 lanes/edge, 4 edges/thread.
__global__ void __launch_bounds__(256)
edge_dot_kernel(const int* __restrict__ ei, long long Eo,
                float* __restrict__ pw, int N)
{
    const int lane = threadIdx.x & 31;
    const int sub = lane & 7;      // 16B chunk within the 128B row
    const int g = lane >> 3;       // edge slot within warp (0..3)
    long long warp_g = ((long long)blockIdx.x * blockDim.x + threadIdx.x) >> 5;
    long long ebase = warp_g * 16;
    if (ebase >= Eo) return;

    int i0[4], i1[4];
    #pragma unroll
    for (int j = 0; j < 4; j++) {
        long long e = ebase + j * 4 + g;
        int a = (e < Eo) ? ei[e] : 0;
        int b = (e < Eo) ? ei[e + Eo] : 0;
        i0[j] = min(max(a, 0), N - 1);
        i1[j] = min(max(b, 0), N - 1);
    }

    uint4 av[4], bv[4];
    #pragma unroll
    for (int j = 0; j < 4; j++) {
        av[j] = ((const uint4*)(g_reps_h + (size_t)i0[j] * 32))[sub];
        bv[j] = ((const uint4*)(g_reps_h + (size_t)i1[j] * 32))[sub];
    }

    float acc[4];
    #pragma unroll
    for (int j = 0; j < 4; j++) {
        acc[j] = dot8h(av[j], bv[j]);
        acc[j] += __shfl_xor_sync(0xffffffffu, acc[j], 4);
        acc[j] += __shfl_xor_sync(0xffffffffu, acc[j], 2);
        acc[j] += __shfl_xor_sync(0xffffffffu, acc[j], 1);
    }

    if (sub == 0) {
        #pragma unroll
        for (int j = 0; j < 4; j++) {
            long long e = ebase + j * 4 + g;
            if (e < Eo) pw[e] = fmaxf(acc[j], 0.f);
        }
    }
}

extern "C" void kernel_launch(void* const* d_in, const int* in_sizes, int n_in,
                              void* d_out, int out_size)
{
    const float* feat = (const float*)d_in[0];
    const int*   ei   = (const int*)d_in[1];
    const int*   pei  = (const int*)d_in[2];
    const float* W1   = (const float*)d_in[3];
    const float* b1   = (const float*)d_in[4];
    const float* W2   = (const float*)d_in[5];
    const float* b2   = (const float*)d_in[6];
    float* out = (float*)d_out;

    const int N        = in_sizes[0] / 128;
    const long long Eo = in_sizes[1] / 2;
    const long long Ec = in_sizes[2] / 2;

    float* reps    = out;
    float* pw      = out + (size_t)N * 64;
    float* out_tei = pw + Eo;
    float* out_ei  = out_tei + 2 * (Eo + Ec);

    cudaFuncSetAttribute(mlp_mma_kernel,
                         cudaFuncAttributeMaxDynamicSharedMemorySize, SMEM_BYTES);

    // One-shot weight conversion (48*256 = 12288 = one thread per element)
    weight_prep_kernel<<<48, 256>>>(W1, W2);

    int mlp_blocks = (N + NODES_PER_BLK - 1) / NODES_PER_BLK;
    long long copy_items = (Eo > Ec ? Eo : Ec);
    int copy_blocks = (int)((copy_items + MLP_THREADS * 4 - 1) / (MLP_THREADS * 4));

    mlp_mma_kernel<<<mlp_blocks + copy_blocks, MLP_THREADS, SMEM_BYTES>>>(
        feat, b1, b2, reps, N, mlp_blocks,
        ei, pei, Eo, Ec, out_tei, out_ei);

    // warps of 16 edges each
    long long warps = (Eo + 15) / 16;
    long long threads = warps * 32;
    int edge_blocks = (int)((threads + 255) / 256);
    edge_dot_kernel<<<edge_blocks, 256>>>(ei, Eo, pw, N);
}